// round 15
// baseline (speedup 1.0000x reference)
#include <cuda_runtime.h>
#include <cuda_bf16.h>
#include <cstdint>

#define BS 32
#define NN 200
#define HD 100
#define NH 34
#define SDIM 1024
#define NRH (NN*HD)   // 20000
#define YW 104
#define WW 104
#define XW 104
#define TRS (NN*XW)   // 20800
#define EPSV 1e-20f

// ygemm dynamic smem layout (4 stages)
#define YG_A_STRIDE 3072           // 64*24*2 bytes per A stage
#define YG_B_STRIDE 3840           // 16*120*2 bytes per B stage
#define YG_AL_OFF   12288          // 4*YG_A_STRIDE
#define YG_BH_OFF   24576
#define YG_BL_OFF   39936
#define YG_SMEM     55296

// agemm dynamic smem layout (5 stages)
#define AG_A_STRIDE 3072
#define AG_B_STRIDE 3840
#define AG_BH_OFF   15360          // 5*AG_A_STRIDE
#define AG_BL_OFF   34560          // 15360 + 5*3840
#define AG_SMEM     53760

// ---------------- scratch ----------------
__device__ __align__(16) __nv_bfloat16 g_Yh[(size_t)BS*NH*NN*YW];
__device__ __align__(16) __nv_bfloat16 g_Yl[(size_t)BS*NH*NN*YW];
__device__ __align__(16) __nv_bfloat16 g_Trh[(size_t)BS*NH*TRS];
__device__ __align__(16) __nv_bfloat16 g_Trl[(size_t)BS*NH*TRS];
__device__ __align__(16) __nv_bfloat16 g_Xh[BS*TRS];
__device__ __align__(16) __nv_bfloat16 g_Xl[BS*TRS];
__device__ __align__(16) __nv_bfloat16 g_Wh[70*HD*WW];
__device__ __align__(16) __nv_bfloat16 g_Wl[70*HD*WW];
__device__ float g_Zh[(size_t)BS*NH*NRH];
__device__ float g_Zsum[BS*NRH];
__device__ float g_D[BS*NH*NN];
__device__ float g_Zt[2*BS*NRH];
__device__ float g_Dt[2*BS*NN];
__device__ float g_Sq[BS*HD];

// ---------------- PTX helpers ----------------
__device__ __forceinline__ uint32_t smem_u32(const void* p) {
    return (uint32_t)__cvta_generic_to_shared(p);
}
__device__ __forceinline__ void ldsm_x4(uint32_t& r0, uint32_t& r1, uint32_t& r2, uint32_t& r3, uint32_t addr) {
    asm volatile("ldmatrix.sync.aligned.m8n8.x4.shared.b16 {%0,%1,%2,%3},[%4];"
                 : "=r"(r0), "=r"(r1), "=r"(r2), "=r"(r3) : "r"(addr));
}
__device__ __forceinline__ void ldsm_x4t(uint32_t& r0, uint32_t& r1, uint32_t& r2, uint32_t& r3, uint32_t addr) {
    asm volatile("ldmatrix.sync.aligned.m8n8.x4.trans.shared.b16 {%0,%1,%2,%3},[%4];"
                 : "=r"(r0), "=r"(r1), "=r"(r2), "=r"(r3) : "r"(addr));
}
__device__ __forceinline__ void ldsm_x2t(uint32_t& r0, uint32_t& r1, uint32_t addr) {
    asm volatile("ldmatrix.sync.aligned.m8n8.x2.trans.shared.b16 {%0,%1},[%2];"
                 : "=r"(r0), "=r"(r1) : "r"(addr));
}
__device__ __forceinline__ void mma16816(float* c, uint32_t a0, uint32_t a1, uint32_t a2, uint32_t a3,
                                         uint32_t b0, uint32_t b1) {
    asm volatile("mma.sync.aligned.m16n8k16.row.col.f32.bf16.bf16.f32 "
                 "{%0,%1,%2,%3},{%4,%5,%6,%7},{%8,%9},{%0,%1,%2,%3};"
                 : "+f"(c[0]), "+f"(c[1]), "+f"(c[2]), "+f"(c[3])
                 : "r"(a0), "r"(a1), "r"(a2), "r"(a3), "r"(b0), "r"(b1));
}
__device__ __forceinline__ void cp16(uint32_t dst, const void* src) {
    asm volatile("cp.async.cg.shared.global [%0], [%1], 16;" :: "r"(dst), "l"(src));
}
__device__ __forceinline__ void cp_commit() { asm volatile("cp.async.commit_group;"); }
template<int N> __device__ __forceinline__ void cp_wait_group() {
    asm volatile("cp.async.wait_group %0;" :: "n"(N));
}

// ---------------- pipelined-GEMM building blocks ----------------
__device__ __forceinline__ float4 loadA16(const float* __restrict__ Ap, int m0, int k0, int tid)
{
    int row = tid >> 2, kp = (tid & 3) * 4;
    int gk = k0 + kp;
    float4 v = make_float4(0.f, 0.f, 0.f, 0.f);
    if (gk + 3 < NN) v = *(const float4*)(Ap + (size_t)(m0 + row) * NN + gk);
    return v;
}
__device__ __forceinline__ void stsA16(float4 v, __nv_bfloat16 (*sA)[24], int tid)
{
    int row = tid >> 2, kp = (tid & 3) * 4;
    __nv_bfloat162 h0 = __floats2bfloat162_rn(v.x, v.y);
    __nv_bfloat162 h1 = __floats2bfloat162_rn(v.z, v.w);
    uint2 p;
    p.x = *reinterpret_cast<uint32_t*>(&h0);
    p.y = *reinterpret_cast<uint32_t*>(&h1);
    *(uint2*)&sA[row][kp] = p;
}
__device__ __forceinline__ void issueB16(const __nv_bfloat16* __restrict__ Bh,
                                         const __nv_bfloat16* __restrict__ Bl,
                                         int k0, int klim, int tid,
                                         __nv_bfloat16 (*sH)[120], __nv_bfloat16 (*sL)[120])
{
    if (tid < 208) {
        int row = tid / 13, cc = tid - row * 13;
        int gj = k0 + row;
        __nv_bfloat16* dh = &sH[row][cc * 8];
        __nv_bfloat16* dl = &sL[row][cc * 8];
        if (gj < klim) {
            cp16(smem_u32(dh), Bh + (size_t)gj * 104 + cc * 8);
            cp16(smem_u32(dl), Bl + (size_t)gj * 104 + cc * 8);
        } else {
            uint4 z = make_uint4(0u, 0u, 0u, 0u);
            *(uint4*)dh = z; *(uint4*)dl = z;
        }
    }
}
__device__ __forceinline__ void issueA16(const __nv_bfloat16* __restrict__ Ah,
                                         const __nv_bfloat16* __restrict__ Al,
                                         int m0, int k0, int tid,
                                         __nv_bfloat16 (*sH)[24], __nv_bfloat16 (*sL)[24])
{
    int row = tid >> 2, q = tid & 3;
    int seg = q & 1;
    int lo = q >> 1;
    int gk = k0 + seg * 8;
    const __nv_bfloat16* src = (lo ? Al : Ah) + (size_t)(m0 + row) * XW + gk;
    __nv_bfloat16* dst = lo ? &sL[row][seg*8] : &sH[row][seg*8];
    if (gk < XW) cp16(smem_u32(dst), src);
    else *(uint4*)dst = make_uint4(0u,0u,0u,0u);
}
// 2-chain compute (A exact bf16): A*Bh + A*Bl.  B via x4.trans pairs.
__device__ __forceinline__ void compute_tile(float (*acc)[4], uint32_t aAddr,
                                             uint32_t bH, uint32_t bL, int wn)
{
    uint32_t a0, a1, a2, a3;
    ldsm_x4(a0, a1, a2, a3, aAddr);
    uint32_t base = (uint32_t)(wn * 56) * 2;
    #pragma unroll
    for (int p = 0; p < 3; ++p) {
        uint32_t off = base + (uint32_t)(p * 16) * 2;
        uint32_t b0, b1, b2, b3;
        ldsm_x4t(b0, b1, b2, b3, bH + off);
        mma16816(acc[2*p],   a0, a1, a2, a3, b0, b1);
        mma16816(acc[2*p+1], a0, a1, a2, a3, b2, b3);
        ldsm_x4t(b0, b1, b2, b3, bL + off);
        mma16816(acc[2*p],   a0, a1, a2, a3, b0, b1);
        mma16816(acc[2*p+1], a0, a1, a2, a3, b2, b3);
    }
    {
        uint32_t off = base + (uint32_t)(6 * 8) * 2;
        uint32_t b0, b1;
        ldsm_x2t(b0, b1, bH + off);
        mma16816(acc[6], a0, a1, a2, a3, b0, b1);
        ldsm_x2t(b0, b1, bL + off);
        mma16816(acc[6], a0, a1, a2, a3, b0, b1);
    }
}
// 3-chain compute (split A, split B): Ah*Bh + Al*Bh + Ah*Bl
__device__ __forceinline__ void compute_tile3(float (*acc)[4], uint32_t aH, uint32_t aL,
                                              uint32_t bH, uint32_t bL, int wn)
{
    uint32_t ah0, ah1, ah2, ah3, al0, al1, al2, al3;
    ldsm_x4(ah0, ah1, ah2, ah3, aH);
    ldsm_x4(al0, al1, al2, al3, aL);
    uint32_t base = (uint32_t)(wn * 56) * 2;
    #pragma unroll
    for (int p = 0; p < 3; ++p) {
        uint32_t off = base + (uint32_t)(p * 16) * 2;
        uint32_t b0, b1, b2, b3;
        ldsm_x4t(b0, b1, b2, b3, bH + off);
        mma16816(acc[2*p],   ah0, ah1, ah2, ah3, b0, b1);
        mma16816(acc[2*p],   al0, al1, al2, al3, b0, b1);
        mma16816(acc[2*p+1], ah0, ah1, ah2, ah3, b2, b3);
        mma16816(acc[2*p+1], al0, al1, al2, al3, b2, b3);
        ldsm_x4t(b0, b1, b2, b3, bL + off);
        mma16816(acc[2*p],   ah0, ah1, ah2, ah3, b0, b1);
        mma16816(acc[2*p+1], ah0, ah1, ah2, ah3, b2, b3);
    }
    {
        uint32_t off = base + (uint32_t)(6 * 8) * 2;
        uint32_t b0, b1;
        ldsm_x2t(b0, b1, bH + off);
        mma16816(acc[6], ah0, ah1, ah2, ah3, b0, b1);
        mma16816(acc[6], al0, al1, al2, al3, b0, b1);
        ldsm_x2t(b0, b1, bL + off);
        mma16816(acc[6], ah0, ah1, ah2, ah3, b0, b1);
    }
}

// ---------------- conversions ----------------
__global__ void k_splitX(const float* __restrict__ src)
{
    int i = blockIdx.x * 256 + threadIdx.x;
    if (i >= BS*TRS) return;
    int col = i % XW;
    int row = i / XW;
    float v = (col < HD) ? src[(size_t)row * HD + col] : 0.f;
    __nv_bfloat16 h = __float2bfloat16(v);
    g_Xh[i] = h;
    g_Xl[i] = __float2bfloat16(v - __bfloat162float(h));
}

__global__ void k_splitW(const float* __restrict__ wvs)
{
    int i = blockIdx.x * 256 + threadIdx.x;
    if (i >= 70*HD*WW) return;
    int col = i % WW;
    int row = i / WW;
    float v = (col < HD) ? wvs[(size_t)row * HD + col] : 0.f;
    __nv_bfloat16 h = __float2bfloat16(v);
    g_Wh[i] = h;
    g_Wl[i] = __float2bfloat16(v - __bfloat162float(h));
}

// ---------------- Sq = S @ wq_w^T + wq_b ----------------
__global__ void k_sq(const float* __restrict__ S, const float* __restrict__ wqw,
                     const float* __restrict__ wqb)
{
    int lane = threadIdx.x & 31;
    int gw = blockIdx.x * 8 + (threadIdx.x >> 5);
    if (gw >= BS*HD) return;
    int b = gw / HD, h = gw % HD;
    const float* sp = S + (size_t)b * SDIM;
    const float* wp = wqw + (size_t)h * SDIM;
    float acc = 0.f;
    for (int k = lane * 4; k < SDIM; k += 128) {
        float4 s4 = *(const float4*)(sp + k);
        float4 w4 = *(const float4*)(wp + k);
        acc += s4.x*w4.x + s4.y*w4.y + s4.z*w4.z + s4.w*w4.w;
    }
    #pragma unroll
    for (int o = 16; o > 0; o >>= 1) acc += __shfl_down_sync(0xffffffffu, acc, o);
    if (lane == 0) g_Sq[b*HD + h] = acc + wqb[h];
}

// ---------------- tensor-core Y GEMM (4-stage K16 via dynamic smem, wait<2>) ----------------
__global__ __launch_bounds__(256) void k_ygemm_tc(int mode, const float* __restrict__ uni,
                                                  const float* __restrict__ start,
                                                  const float* __restrict__ trans)
{
    extern __shared__ char dsm[];
    __nv_bfloat16 (*sAh)[64][24]  = (__nv_bfloat16(*)[64][24])(dsm);
    __nv_bfloat16 (*sAl)[64][24]  = (__nv_bfloat16(*)[64][24])(dsm + YG_AL_OFF);
    __nv_bfloat16 (*sBh)[16][120] = (__nv_bfloat16(*)[16][120])(dsm + YG_BH_OFF);
    __nv_bfloat16 (*sBl)[16][120] = (__nv_bfloat16(*)[16][120])(dsm + YG_BL_OFF);

    int r = blockIdx.x, b = blockIdx.y, z = blockIdx.z;
    int m0 = (z == 3) ? 136 : z * 64;

    const __nv_bfloat16 *Ah, *Al, *Wh, *Wl;
    if (mode == 0) {
        Ah = g_Xh + (size_t)b * TRS;  Al = g_Xl + (size_t)b * TRS;
        Wh = g_Wh + (size_t)r * HD * WW;  Wl = g_Wl + (size_t)r * HD * WW;
    } else {
        Ah = g_Trh + (size_t)(b*NH + r) * TRS;  Al = g_Trl + (size_t)(b*NH + r) * TRS;
        Wh = g_Wh + (size_t)(35 + r) * HD * WW;  Wl = g_Wl + (size_t)(35 + r) * HD * WW;
    }
    float cs = uni[b*NH + r];
    __nv_bfloat16* Oh = g_Yh + (size_t)(b*NH + r) * NN * YW;
    __nv_bfloat16* Ol = g_Yl + (size_t)(b*NH + r) * NN * YW;

    int tid = threadIdx.x, lane = tid & 31, wid = tid >> 5;
    int wm = wid & 3, wn = wid >> 2;

    {
        int st = tid >> 6;
        int rem = tid & 63;
        int arr = rem >> 5, row = (rem >> 1) & 15, sg = rem & 1;
        __nv_bfloat16* p = arr ? &sBl[st][row][104 + sg*8] : &sBh[st][row][104 + sg*8];
        *(uint4*)p = make_uint4(0u,0u,0u,0u);
    }

    float acc[7][4];
    #pragma unroll
    for (int f = 0; f < 7; ++f)
        #pragma unroll
        for (int q = 0; q < 4; ++q) acc[f][q] = 0.f;

    uint32_t aHBase = smem_u32(&sAh[0][wm*16 + (lane & 15)][(lane >> 4) * 8]);
    uint32_t aLBase = smem_u32(&sAl[0][wm*16 + (lane & 15)][(lane >> 4) * 8]);
    uint32_t bHBase = smem_u32(&sBh[0][lane & 15][(lane >> 4) * 8]);
    uint32_t bLBase = smem_u32(&sBl[0][lane & 15][(lane >> 4) * 8]);

    issueA16(Ah, Al, m0, 0, tid, sAh[0], sAl[0]);
    issueB16(Wh, Wl, 0, HD, tid, sBh[0], sBl[0]);
    cp_commit();
    issueA16(Ah, Al, m0, 16, tid, sAh[1], sAl[1]);
    issueB16(Wh, Wl, 16, HD, tid, sBh[1], sBl[1]);
    cp_commit();
    issueA16(Ah, Al, m0, 32, tid, sAh[2], sAl[2]);
    issueB16(Wh, Wl, 32, HD, tid, sBh[2], sBl[2]);
    cp_commit();

    #pragma unroll 1
    for (int c = 0; c < 7; ++c) {
        cp_wait_group<2>();
        __syncthreads();
        int nc = c + 3;
        if (nc < 7) {
            int st = nc & 3;
            issueA16(Ah, Al, m0, nc * 16, tid, sAh[st], sAl[st]);
            issueB16(Wh, Wl, nc * 16, HD, tid, sBh[st], sBl[st]);
        }
        cp_commit();
        int s = c & 3;
        compute_tile3(acc, aHBase + s*YG_A_STRIDE, aLBase + s*YG_A_STRIDE,
                      bHBase + s*YG_B_STRIDE, bLBase + s*YG_B_STRIDE, wn);
    }

    int g = lane >> 2, tg = lane & 3;
    #pragma unroll
    for (int f = 0; f < 7; ++f) {
        int c = wn*56 + f*8 + tg*2;
        if (c + 1 >= YW) continue;
        #pragma unroll
        for (int h2 = 0; h2 < 2; ++h2) {
            int row = m0 + wm*16 + g + h2*8;
            if (row >= NN) continue;
            float v0, v1;
            if (c <= 98) {
                float sc = cs * (mode == 0 ? start[b*NN + row] : 1.f);
                v0 = acc[f][2*h2] * sc;
                v1 = acc[f][2*h2 + 1] * sc;
            } else if (c == HD) {
                float dv;
                if (mode == 0) {
                    dv = cs * start[b*NN + row];
                } else {
                    float a = 0.f;
                    #pragma unroll 2
                    for (int rr = 0; rr < NH; ++rr)
                        a += g_D[(b*NH + rr)*NN + row] * trans[(b*NH + rr)*NH + r];
                    dv = cs * a;
                }
                v0 = dv; v1 = 0.f;
            } else {
                v0 = 0.f; v1 = 0.f;
            }
            __nv_bfloat16 h0 = __float2bfloat16(v0);
            __nv_bfloat16 h1 = __float2bfloat16(v1);
            __nv_bfloat162 hh; hh.x = h0; hh.y = h1;
            __nv_bfloat162 ll;
            ll.x = __float2bfloat16(v0 - __bfloat162float(h0));
            ll.y = __float2bfloat16(v1 - __bfloat162float(h1));
            size_t o = (size_t)row * YW + c;
            *(__nv_bfloat162*)(Oh + o) = hh;
            *(__nv_bfloat162*)(Ol + o) = ll;
        }
    }
}

// ---------------- t=0 A-GEMM (5-stage K16 via dynamic smem, wait<3>) ----------------
__global__ __launch_bounds__(256) void k_agemm_tc(const float* __restrict__ A)
{
    extern __shared__ char dsm[];
    __nv_bfloat16 (*sA)[64][24]   = (__nv_bfloat16(*)[64][24])(dsm);
    __nv_bfloat16 (*sBh)[16][120] = (__nv_bfloat16(*)[16][120])(dsm + AG_BH_OFF);
    __nv_bfloat16 (*sBl)[16][120] = (__nv_bfloat16(*)[16][120])(dsm + AG_BL_OFF);

    int r = blockIdx.x, b = blockIdx.y, z = blockIdx.z;
    int m0 = (z == 3) ? 136 : z * 64;

    const float* Ap = A + (size_t)(b*NH + r) * NN * NN;
    const __nv_bfloat16* Yh = g_Yh + (size_t)(b*NH + r) * NN * YW;
    const __nv_bfloat16* Yl = g_Yl + (size_t)(b*NH + r) * NN * YW;
    float* Zb = g_Zh + (size_t)(b*NH + r) * NRH;
    float* Db = g_D + (b*NH + r) * NN;

    int tid = threadIdx.x, lane = tid & 31, wid = tid >> 5;
    int wm = wid & 3, wn = wid >> 2;

    // zero ldsm pad cols 104..119 (5 stages x 2 arrays x 16 rows x 2 segs = 320 units)
    for (int u = tid; u < 320; u += 256) {
        int st = u >> 6;
        int rem = u & 63;
        int arr = rem >> 5, row = (rem >> 1) & 15, sg = rem & 1;
        __nv_bfloat16* p = arr ? &sBl[st][row][104 + sg*8] : &sBh[st][row][104 + sg*8];
        *(uint4*)p = make_uint4(0u,0u,0u,0u);
    }

    float acc[7][4];
    #pragma unroll
    for (int f = 0; f < 7; ++f)
        #pragma unroll
        for (int q = 0; q < 4; ++q) acc[f][q] = 0.f;

    uint32_t aBase = smem_u32(&sA[0][wm*16 + (lane & 15)][(lane >> 4) * 8]);
    uint32_t bHBase = smem_u32(&sBh[0][lane & 15][(lane >> 4) * 8]);
    uint32_t bLBase = smem_u32(&sBl[0][lane & 15][(lane >> 4) * 8]);

    // prologue: stage chunks 0..3; av = chunk 4
    float4 av = loadA16(Ap, m0, 0, tid);
    issueB16(Yh, Yl, 0, NN, tid, sBh[0], sBl[0]);
    cp_commit();
    stsA16(av, sA[0], tid);
    av = loadA16(Ap, m0, 16, tid);
    issueB16(Yh, Yl, 16, NN, tid, sBh[1], sBl[1]);
    cp_commit();
    stsA16(av, sA[1], tid);
    av = loadA16(Ap, m0, 32, tid);
    issueB16(Yh, Yl, 32, NN, tid, sBh[2], sBl[2]);
    cp_commit();
    stsA16(av, sA[2], tid);
    av = loadA16(Ap, m0, 48, tid);
    issueB16(Yh, Yl, 48, NN, tid, sBh[3], sBl[3]);
    cp_commit();
    stsA16(av, sA[3], tid);
    av = loadA16(Ap, m0, 64, tid);

    #pragma unroll 1
    for (int i = 0; i < 13; ++i) {
        cp_wait_group<3>();
        __syncthreads();
        int nc = i + 4;
        if (nc < 13)
            issueB16(Yh, Yl, nc * 16, NN, tid, sBh[nc % 5], sBl[nc % 5]);
        cp_commit();
        int s = i % 5;
        compute_tile(acc, aBase + s*AG_A_STRIDE, bHBase + s*AG_B_STRIDE, bLBase + s*AG_B_STRIDE, wn);
        if (nc < 13) {
            stsA16(av, sA[nc % 5], tid);
            if (nc + 1 < 13) av = loadA16(Ap, m0, (nc + 1) * 16, tid);
        }
    }

    int g = lane >> 2, tg = lane & 3;
    #pragma unroll
    for (int f = 0; f < 7; ++f) {
        int c = wn*56 + f*8 + tg*2;
        #pragma unroll
        for (int h2 = 0; h2 < 2; ++h2) {
            int row = m0 + wm*16 + g + h2*8;
            if (row >= NN) continue;
            if (c <= 98)
                *(float2*)(Zb + row*HD + c) = make_float2(acc[f][2*h2], acc[f][2*h2 + 1]);
            else if (c == HD)
                Db[row] = acc[f][2*h2];
        }
    }
}

// ---------------- zero Zt1/Dt1 accumulators ----------------
__global__ void k_zero1()
{
    int i = blockIdx.x * 256 + threadIdx.x;
    if (i < BS*NRH) g_Zt[(size_t)BS*NRH + i] = 0.f;
    if (i < BS*NN)  g_Dt[BS*NN + i] = 0.f;
}

// ---------------- t=1 grouped A-GEMM (5-stage K16, wait<3>): atomic partials, 4 heads/CTA ----------------
__global__ __launch_bounds__(256) void k_agemm1_tc(const float* __restrict__ A,
                                                   const float* __restrict__ endv)
{
    extern __shared__ char dsm[];
    __nv_bfloat16 (*sA)[64][24]   = (__nv_bfloat16(*)[64][24])(dsm);
    __nv_bfloat16 (*sBh)[16][120] = (__nv_bfloat16(*)[16][120])(dsm + AG_BH_OFF);
    __nv_bfloat16 (*sBl)[16][120] = (__nv_bfloat16(*)[16][120])(dsm + AG_BL_OFF);

    int z = blockIdx.x, b = blockIdx.y, rg = blockIdx.z;
    int m0 = (z == 3) ? 136 : z * 64;
    int rbase = rg * 4;
    int nr = min(4, NH - rbase);
    const int NCH = nr * 13;

    int tid = threadIdx.x, lane = tid & 31, wid = tid >> 5;
    int wm = wid & 3, wn = wid >> 2;

    for (int u = tid; u < 320; u += 256) {
        int st = u >> 6;
        int rem = u & 63;
        int arr = rem >> 5, row = (rem >> 1) & 15, sg = rem & 1;
        __nv_bfloat16* p = arr ? &sBl[st][row][104 + sg*8] : &sBh[st][row][104 + sg*8];
        *(uint4*)p = make_uint4(0u,0u,0u,0u);
    }

    float acc[7][4];
    #pragma unroll
    for (int f = 0; f < 7; ++f)
        #pragma unroll
        for (int q = 0; q < 4; ++q) acc[f][q] = 0.f;

    uint32_t aBase = smem_u32(&sA[0][wm*16 + (lane & 15)][(lane >> 4) * 8]);
    uint32_t bHBase = smem_u32(&sBh[0][lane & 15][(lane >> 4) * 8]);
    uint32_t bLBase = smem_u32(&sBl[0][lane & 15][(lane >> 4) * 8]);

    auto chunkPtrs = [&](int idx, const float*& Ap, const __nv_bfloat16*& Yh,
                         const __nv_bfloat16*& Yl, int& cn) {
        int rn = rbase + idx / 13; cn = idx % 13;
        Ap = A + (size_t)(b*NH + rn) * NN * NN;
        Yh = g_Yh + (size_t)(b*NH + rn) * NN * YW;
        Yl = g_Yl + (size_t)(b*NH + rn) * NN * YW;
    };

    // prologue: stage chunks 0..3; av = chunk 4
    const float* Ap; const __nv_bfloat16 *Yh, *Yl; int cn;
    chunkPtrs(0, Ap, Yh, Yl, cn);
    float4 av = loadA16(Ap, m0, 0, tid);
    issueB16(Yh, Yl, 0, NN, tid, sBh[0], sBl[0]);
    cp_commit();
    stsA16(av, sA[0], tid);
    #pragma unroll 1
    for (int pc = 1; pc <= 3; ++pc) {
        chunkPtrs(pc, Ap, Yh, Yl, cn);
        av = loadA16(Ap, m0, cn * 16, tid);
        issueB16(Yh, Yl, cn * 16, NN, tid, sBh[pc], sBl[pc]);
        cp_commit();
        stsA16(av, sA[pc], tid);
    }
    chunkPtrs(4, Ap, Yh, Yl, cn);
    av = loadA16(Ap, m0, cn * 16, tid);

    #pragma unroll 1
    for (int i = 0; i < NCH; ++i) {
        cp_wait_group<3>();
        __syncthreads();
        int nc = i + 4;
        if (nc < NCH) {
            const float* Ap2; const __nv_bfloat16 *Yh2, *Yl2; int cn2;
            chunkPtrs(nc, Ap2, Yh2, Yl2, cn2);
            issueB16(Yh2, Yl2, cn2 * 16, NN, tid, sBh[nc % 5], sBl[nc % 5]);
        }
        cp_commit();
        int s = i % 5;
        compute_tile(acc, aBase + s*AG_A_STRIDE, bHBase + s*AG_B_STRIDE, bLBase + s*AG_B_STRIDE, wn);
        if (nc < NCH) {
            stsA16(av, sA[nc % 5], tid);
            if (nc + 1 < NCH) {
                chunkPtrs(nc + 1, Ap, Yh, Yl, cn);
                av = loadA16(Ap, m0, cn * 16, tid);
            }
        }
    }

    int rowlo = (z == 3) ? 192 : m0;
    int g = lane >> 2, tg = lane & 3;
    #pragma unroll
    for (int f = 0; f < 7; ++f) {
        int nb = wn*56 + f*8;
        #pragma unroll
        for (int q = 0; q < 4; ++q) {
            int row = m0 + wm*16 + g + (q >> 1) * 8;
            int col = nb + tg*2 + (q & 1);
            if (row >= rowlo && row < NN) {
                float e = endv[b*NN + row];
                if (col < HD)
                    atomicAdd(&g_Zt[(size_t)(BS + b) * NRH + row*HD + col], acc[f][q] * e);
                else if (col == HD)
                    atomicAdd(&g_Dt[BS*NN + b*NN + row], acc[f][q] * e);
            }
        }
    }
}

// ---------------- Dt0[b,i] = end * sum_r D0[b,r,i] ----------------
__global__ void k_dt(const float* __restrict__ endv)
{
    int idx = blockIdx.x * 256 + threadIdx.x;
    if (idx >= BS*NN) return;
    int b = idx / NN, i = idx - b*NN;
    float acc = 0.f;
    #pragma unroll 2
    for (int r = 0; r < NH; ++r) acc += g_D[(b*NH + r)*NN + i];
    g_Dt[idx] = acc * endv[idx];
}

// ---------------- fused trans-mix + r-sum over Zh0 ----------------
__global__ void k_transsum(const float* __restrict__ trans)
{
    int b = blockIdx.y;
    __shared__ float ts[NH*NH];
    for (int i = threadIdx.x; i < NH*NH; i += 256) ts[i] = trans[b*NH*NH + i];
    __syncthreads();

    int x0 = blockIdx.x * 512 + threadIdx.x;
    int x1 = x0 + 256;
    const float* Zb = g_Zh + (size_t)b * NH * NRH;
    float acc0[NH], acc1[NH];
    float sv0 = 0.f, sv1 = 0.f;
    #pragma unroll
    for (int s = 0; s < NH; ++s) { acc0[s] = 0.f; acc1[s] = 0.f; }

    for (int r = 0; r < NH; ++r) {
        float v0 = (x0 < NRH) ? Zb[(size_t)r*NRH + x0] : 0.f;
        float v1 = (x1 < NRH) ? Zb[(size_t)r*NRH + x1] : 0.f;
        sv0 += v0; sv1 += v1;
        #pragma unroll
        for (int s = 0; s < NH; ++s) {
            float tv = ts[r*NH + s];
            acc0[s] += v0 * tv;
            acc1[s] += v1 * tv;
        }
    }
    int j0 = x0 / HD, d0 = x0 - j0*HD;
    int j1 = x1 / HD, d1 = x1 - j1*HD;
    size_t p0 = (size_t)j0 * XW + d0;
    size_t p1 = (size_t)j1 * XW + d1;
    #pragma unroll
    for (int s = 0; s < NH; ++s) {
        size_t ob = (size_t)(b*NH + s) * TRS;
        if (x0 < NRH) {
            float v = acc0[s];
            __nv_bfloat16 h = __float2bfloat16(v);
            g_Trh[ob + p0] = h;
            g_Trl[ob + p0] = __float2bfloat16(v - __bfloat162float(h));
            if (d0 >= 96) { g_Trh[ob + p0 + 4] = __float2bfloat16(0.f);
                            g_Trl[ob + p0 + 4] = __float2bfloat16(0.f); }
        }
        if (x1 < NRH) {
            float v = acc1[s];
            __nv_bfloat16 h = __float2bfloat16(v);
            g_Trh[ob + p1] = h;
            g_Trl[ob + p1] = __float2bfloat16(v - __bfloat162float(h));
            if (d1 >= 96) { g_Trh[ob + p1 + 4] = __float2bfloat16(0.f);
                            g_Trl[ob + p1 + 4] = __float2bfloat16(0.f); }
        }
    }
    if (x0 < NRH) g_Zsum[(size_t)b * NRH + x0] = sv0;
    if (x1 < NRH) g_Zsum[(size_t)b * NRH + x1] = sv1;
}

// ---------------- Zt0 = rowscale(end) * (Zsum[b] @ Wpad)  grid (2, BS) ----------------
__global__ void k_zt0(const float* __restrict__ wvs, const float* __restrict__ endv)
{
    int mt = blockIdx.x;
    int b = blockIdx.y;
    const float* In = g_Zsum + (size_t)b * NRH;
    const float* W = wvs + (size_t)69 * (HD*HD);
    const float* rs = endv + b*NN;
    float* Out = g_Zt + (size_t)b * NRH;

    __shared__ float As[128][33];
    __shared__ float Bs[32][128];
    int tid = threadIdx.x;
    int tx = tid & 15, ty = tid >> 4;

    float acc[8][8];
    #pragma unroll
    for (int i = 0; i < 8; ++i)
        #pragma unroll
        for (int j = 0; j < 8; ++j) acc[i][j] = 0.f;

    for (int k0 = 0; k0 < HD; k0 += 32) {
        int klen = min(32, HD - k0);
        #pragma unroll
        for (int l = 0; l < 4; ++l) {
            int idx = tid + l*256;
            int row = idx >> 3;
            int c4 = (idx & 7) << 2;
            int grow = mt*128 + row;
            float4 v = make_float4(0.f,0.f,0.f,0.f);
            if (grow < NN && c4 < klen)
                v = *(const float4*)(In + (size_t)grow*HD + k0 + c4);
            As[row][c4+0] = v.x; As[row][c4+1] = v.y;
            As[row][c4+2] = v.z; As[row][c4+3] = v.w;
        }
        #pragma unroll
        for (int l = 0; l < 4; ++l) {
            int idx = tid + l*256;
            int kk = idx >> 5;
            int c4 = (idx & 31) << 2;
            float4 v = make_float4(0.f,0.f,0.f,0.f);
            if (kk < klen && c4 < HD)
                v = *(const float4*)(W + (size_t)(k0+kk)*HD + c4);
            *(float4*)&Bs[kk][c4] = v;
        }
        __syncthreads();
        #pragma unroll 4
        for (int kk = 0; kk < klen; ++kk) {
            float a[8];
            #pragma unroll
            for (int i = 0; i < 8; ++i) a[i] = As[ty*8 + i][kk];
            float4 b0 = *(float4*)&Bs[kk][tx*8];
            float4 b1 = *(float4*)&Bs[kk][tx*8 + 4];
            float bb[8] = {b0.x,b0.y,b0.z,b0.w,b1.x,b1.y,b1.z,b1.w};
            #pragma unroll
            for (int i = 0; i < 8; ++i)
                #pragma unroll
                for (int j = 0; j < 8; ++j)
                    acc[i][j] += a[i] * bb[j];
        }
        __syncthreads();
    }
    #pragma unroll
    for (int i = 0; i < 8; ++i) {
        int grow = mt*128 + ty*8 + i;
        if (grow < NN) {
            float sc = rs[grow];
            #pragma unroll
            for (int j = 0; j < 8; ++j) {
                int c = tx*8 + j;
                if (c < HD) Out[(size_t)grow*HD + c] = acc[i][j] * sc;
            }
        }
    }
}

// ---------------- epilogue ----------------
__global__ void k_out(float* __restrict__ out)
{
    int bn = blockIdx.x;
    int b = bn / NN, n = bn - b*NN;
    int tid = threadIdx.x;
    __shared__ float red[128];

    float z[2], dt[2];
    #pragma unroll
    for (int t = 0; t < 2; ++t) {
        float zv = 0.f;
        if (tid < HD) {
            float dd = g_Dt[t*BS*NN + b*NN + n];
            zv = g_Zt[(size_t)(t*BS + b) * NRH + n*HD + tid] / (dd + EPSV);
        }
        z[t] = zv;
        red[tid] = (tid < HD) ? g_Sq[b*HD + tid] * zv : 0.f;
        __syncthreads();
        for (int s = 64; s > 0; s >>= 1) {
            if (tid < s) red[tid] += red[tid + s];
            __syncthreads();
        }
        dt[t] = red[0] * 0.1f;
        __syncthreads();
    }
    float m = fmaxf(dt[0], dt[1]);
    float e0 = expf(dt[0] - m), e1 = expf(dt[1] - m);
    float inv = 1.f / (e0 + e1);
    if (tid < HD)
        out[(size_t)bn * HD + tid] = (e0 * z[0] + e1 * z[1]) * inv;
}

// ---------------- launch (multi-stream, graph-capturable fork/join) ----------------
extern "C" void kernel_launch(void* const* d_in, const int* in_sizes, int n_in,
                              void* d_out, int out_size)
{
    (void)in_sizes; (void)n_in; (void)out_size;
    const float* X     = (const float*)d_in[0];
    const float* A     = (const float*)d_in[1];
    const float* start = (const float*)d_in[2];
    const float* endv  = (const float*)d_in[3];
    const float* uni   = (const float*)d_in[4];
    const float* trans = (const float*)d_in[5];
    const float* S     = (const float*)d_in[6];
    const float* wvs   = (const float*)d_in[7];
    const float* wqw   = (const float*)d_in[8];
    const float* wqb   = (const float*)d_in[9];
    float* out = (float*)d_out;

    static cudaStream_t s1, s2, s3;
    static cudaEvent_t e0, e1, e2, e3, e4, e5, e6;
    static bool init = false;
    if (!init) {
        cudaStreamCreateWithFlags(&s1, cudaStreamNonBlocking);
        cudaStreamCreateWithFlags(&s2, cudaStreamNonBlocking);
        cudaStreamCreateWithFlags(&s3, cudaStreamNonBlocking);
        cudaEventCreateWithFlags(&e0, cudaEventDisableTiming);
        cudaEventCreateWithFlags(&e1, cudaEventDisableTiming);
        cudaEventCreateWithFlags(&e2, cudaEventDisableTiming);
        cudaEventCreateWithFlags(&e3, cudaEventDisableTiming);
        cudaEventCreateWithFlags(&e4, cudaEventDisableTiming);
        cudaEventCreateWithFlags(&e5, cudaEventDisableTiming);
        cudaEventCreateWithFlags(&e6, cudaEventDisableTiming);
        cudaFuncSetAttribute((const void*)k_ygemm_tc,
                             cudaFuncAttributeMaxDynamicSharedMemorySize, YG_SMEM);
        cudaFuncSetAttribute((const void*)k_agemm_tc,
                             cudaFuncAttributeMaxDynamicSharedMemorySize, AG_SMEM);
        cudaFuncSetAttribute((const void*)k_agemm1_tc,
                             cudaFuncAttributeMaxDynamicSharedMemorySize, AG_SMEM);
        init = true;
    }

    cudaEventRecord(e0, 0);
    cudaStreamWaitEvent(s1, e0, 0);
    cudaStreamWaitEvent(s2, e0, 0);
    cudaStreamWaitEvent(s3, e0, 0);

    k_sq<<<(BS*HD + 7) / 8, 256, 0, s1>>>(S, wqw, wqb);
    k_splitW<<<(70*HD*WW + 255)/256, 256, 0, s2>>>(wvs);
    k_zero1<<<(BS*NRH + 255)/256, 256, 0, s3>>>();
    k_splitX<<<(BS*TRS + 255)/256, 256>>>(X);

    cudaEventRecord(e1, s2);
    cudaStreamWaitEvent(0, e1, 0);

    dim3 gg(NH, BS, 4);
    k_ygemm_tc<<<gg, 256, YG_SMEM>>>(0, uni, start, trans);
    k_agemm_tc<<<gg, 256, AG_SMEM>>>(A);

    cudaEventRecord(e2, 0);
    cudaStreamWaitEvent(s1, e2, 0);
    k_dt<<<(BS*NN + 255)/256, 256, 0, s1>>>(endv);

    k_transsum<<<dim3((NRH + 511)/512, BS), 256>>>(trans);

    cudaEventRecord(e3, 0);
    cudaStreamWaitEvent(s2, e3, 0);
    k_zt0<<<dim3(2, BS), 256, 0, s2>>>(wvs, endv);

    k_ygemm_tc<<<gg, 256, YG_SMEM>>>(1, uni, start, trans);
    cudaEventRecord(e4, s3);
    cudaStreamWaitEvent(0, e4, 0);
    k_agemm1_tc<<<dim3(4, BS, 9), 256, AG_SMEM>>>(A, endv);

    cudaEventRecord(e5, s1);
    cudaStreamWaitEvent(0, e5, 0);
    cudaEventRecord(e6, s2);
    cudaStreamWaitEvent(0, e6, 0);
    k_out<<<BS*NN, 128>>>(out);
}

// round 16
// speedup vs baseline: 1.0889x; 1.0889x over previous
#include <cuda_runtime.h>
#include <cuda_bf16.h>
#include <cstdint>

#define BS 32
#define NN 200
#define HD 100
#define NH 34
#define SDIM 1024
#define NRH (NN*HD)   // 20000
#define YW 104
#define WW 104
#define XW 104
#define TRS (NN*XW)   // 20800
#define EPSV 1e-20f

// ygemm dynamic smem layout (4 stages)
#define YG_A_STRIDE 3072
#define YG_B_STRIDE 3840
#define YG_AL_OFF   12288
#define YG_BH_OFF   24576
#define YG_BL_OFF   39936
#define YG_SMEM     55296

// ---------------- scratch ----------------
__device__ __align__(16) __nv_bfloat16 g_Yh[(size_t)BS*NH*NN*YW];
__device__ __align__(16) __nv_bfloat16 g_Yl[(size_t)BS*NH*NN*YW];
__device__ __align__(16) __nv_bfloat16 g_Trh[(size_t)BS*NH*TRS];
__device__ __align__(16) __nv_bfloat16 g_Trl[(size_t)BS*NH*TRS];
__device__ __align__(16) __nv_bfloat16 g_Xh[BS*TRS];
__device__ __align__(16) __nv_bfloat16 g_Xl[BS*TRS];
__device__ __align__(16) __nv_bfloat16 g_Wh[70*HD*WW];
__device__ __align__(16) __nv_bfloat16 g_Wl[70*HD*WW];
__device__ float g_Zh[(size_t)BS*NH*NRH];
__device__ float g_Zsum[BS*NRH];
__device__ float g_D[BS*NH*NN];
__device__ float g_Zt[2*BS*NRH];
__device__ float g_Dt[2*BS*NN];
__device__ float g_Sq[BS*HD];

// ---------------- PTX helpers ----------------
__device__ __forceinline__ uint32_t smem_u32(const void* p) {
    return (uint32_t)__cvta_generic_to_shared(p);
}
__device__ __forceinline__ void ldsm_x4(uint32_t& r0, uint32_t& r1, uint32_t& r2, uint32_t& r3, uint32_t addr) {
    asm volatile("ldmatrix.sync.aligned.m8n8.x4.shared.b16 {%0,%1,%2,%3},[%4];"
                 : "=r"(r0), "=r"(r1), "=r"(r2), "=r"(r3) : "r"(addr));
}
__device__ __forceinline__ void ldsm_x4t(uint32_t& r0, uint32_t& r1, uint32_t& r2, uint32_t& r3, uint32_t addr) {
    asm volatile("ldmatrix.sync.aligned.m8n8.x4.trans.shared.b16 {%0,%1,%2,%3},[%4];"
                 : "=r"(r0), "=r"(r1), "=r"(r2), "=r"(r3) : "r"(addr));
}
__device__ __forceinline__ void ldsm_x2t(uint32_t& r0, uint32_t& r1, uint32_t addr) {
    asm volatile("ldmatrix.sync.aligned.m8n8.x2.trans.shared.b16 {%0,%1},[%2];"
                 : "=r"(r0), "=r"(r1) : "r"(addr));
}
__device__ __forceinline__ void mma16816(float* c, uint32_t a0, uint32_t a1, uint32_t a2, uint32_t a3,
                                         uint32_t b0, uint32_t b1) {
    asm volatile("mma.sync.aligned.m16n8k16.row.col.f32.bf16.bf16.f32 "
                 "{%0,%1,%2,%3},{%4,%5,%6,%7},{%8,%9},{%0,%1,%2,%3};"
                 : "+f"(c[0]), "+f"(c[1]), "+f"(c[2]), "+f"(c[3])
                 : "r"(a0), "r"(a1), "r"(a2), "r"(a3), "r"(b0), "r"(b1));
}
__device__ __forceinline__ void cp16(uint32_t dst, const void* src) {
    asm volatile("cp.async.cg.shared.global [%0], [%1], 16;" :: "r"(dst), "l"(src));
}
__device__ __forceinline__ void cp_commit() { asm volatile("cp.async.commit_group;"); }
template<int N> __device__ __forceinline__ void cp_wait_group() {
    asm volatile("cp.async.wait_group %0;" :: "n"(N));
}

// ---------------- pipelined-GEMM building blocks ----------------
__device__ __forceinline__ float4 loadA16(const float* __restrict__ Ap, int m0, int k0, int tid)
{
    int row = tid >> 2, kp = (tid & 3) * 4;
    int gk = k0 + kp;
    float4 v = make_float4(0.f, 0.f, 0.f, 0.f);
    if (gk + 3 < NN) v = *(const float4*)(Ap + (size_t)(m0 + row) * NN + gk);
    return v;
}
__device__ __forceinline__ void stsA16(float4 v, __nv_bfloat16 (*sA)[24], int tid)
{
    int row = tid >> 2, kp = (tid & 3) * 4;
    __nv_bfloat162 h0 = __floats2bfloat162_rn(v.x, v.y);
    __nv_bfloat162 h1 = __floats2bfloat162_rn(v.z, v.w);
    uint2 p;
    p.x = *reinterpret_cast<uint32_t*>(&h0);
    p.y = *reinterpret_cast<uint32_t*>(&h1);
    *(uint2*)&sA[row][kp] = p;
}
__device__ __forceinline__ void issueB16(const __nv_bfloat16* __restrict__ Bh,
                                         const __nv_bfloat16* __restrict__ Bl,
                                         int k0, int klim, int tid,
                                         __nv_bfloat16 (*sH)[120], __nv_bfloat16 (*sL)[120])
{
    if (tid < 208) {
        int row = tid / 13, cc = tid - row * 13;
        int gj = k0 + row;
        __nv_bfloat16* dh = &sH[row][cc * 8];
        __nv_bfloat16* dl = &sL[row][cc * 8];
        if (gj < klim) {
            cp16(smem_u32(dh), Bh + (size_t)gj * 104 + cc * 8);
            cp16(smem_u32(dl), Bl + (size_t)gj * 104 + cc * 8);
        } else {
            uint4 z = make_uint4(0u, 0u, 0u, 0u);
            *(uint4*)dh = z; *(uint4*)dl = z;
        }
    }
}
__device__ __forceinline__ void issueA16(const __nv_bfloat16* __restrict__ Ah,
                                         const __nv_bfloat16* __restrict__ Al,
                                         int m0, int k0, int tid,
                                         __nv_bfloat16 (*sH)[24], __nv_bfloat16 (*sL)[24])
{
    int row = tid >> 2, q = tid & 3;
    int seg = q & 1;
    int lo = q >> 1;
    int gk = k0 + seg * 8;
    const __nv_bfloat16* src = (lo ? Al : Ah) + (size_t)(m0 + row) * XW + gk;
    __nv_bfloat16* dst = lo ? &sL[row][seg*8] : &sH[row][seg*8];
    if (gk < XW) cp16(smem_u32(dst), src);
    else *(uint4*)dst = make_uint4(0u,0u,0u,0u);
}
__device__ __forceinline__ void compute_tile(float (*acc)[4], uint32_t aAddr,
                                             uint32_t bH, uint32_t bL, int wn)
{
    uint32_t a0, a1, a2, a3;
    ldsm_x4(a0, a1, a2, a3, aAddr);
    uint32_t base = (uint32_t)(wn * 56) * 2;
    #pragma unroll
    for (int p = 0; p < 3; ++p) {
        uint32_t off = base + (uint32_t)(p * 16) * 2;
        uint32_t b0, b1, b2, b3;
        ldsm_x4t(b0, b1, b2, b3, bH + off);
        mma16816(acc[2*p],   a0, a1, a2, a3, b0, b1);
        mma16816(acc[2*p+1], a0, a1, a2, a3, b2, b3);
        ldsm_x4t(b0, b1, b2, b3, bL + off);
        mma16816(acc[2*p],   a0, a1, a2, a3, b0, b1);
        mma16816(acc[2*p+1], a0, a1, a2, a3, b2, b3);
    }
    {
        uint32_t off = base + (uint32_t)(6 * 8) * 2;
        uint32_t b0, b1;
        ldsm_x2t(b0, b1, bH + off);
        mma16816(acc[6], a0, a1, a2, a3, b0, b1);
        ldsm_x2t(b0, b1, bL + off);
        mma16816(acc[6], a0, a1, a2, a3, b0, b1);
    }
}
__device__ __forceinline__ void compute_tile3(float (*acc)[4], uint32_t aH, uint32_t aL,
                                              uint32_t bH, uint32_t bL, int wn)
{
    uint32_t ah0, ah1, ah2, ah3, al0, al1, al2, al3;
    ldsm_x4(ah0, ah1, ah2, ah3, aH);
    ldsm_x4(al0, al1, al2, al3, aL);
    uint32_t base = (uint32_t)(wn * 56) * 2;
    #pragma unroll
    for (int p = 0; p < 3; ++p) {
        uint32_t off = base + (uint32_t)(p * 16) * 2;
        uint32_t b0, b1, b2, b3;
        ldsm_x4t(b0, b1, b2, b3, bH + off);
        mma16816(acc[2*p],   ah0, ah1, ah2, ah3, b0, b1);
        mma16816(acc[2*p],   al0, al1, al2, al3, b0, b1);
        mma16816(acc[2*p+1], ah0, ah1, ah2, ah3, b2, b3);
        mma16816(acc[2*p+1], al0, al1, al2, al3, b2, b3);
        ldsm_x4t(b0, b1, b2, b3, bL + off);
        mma16816(acc[2*p],   ah0, ah1, ah2, ah3, b0, b1);
        mma16816(acc[2*p+1], ah0, ah1, ah2, ah3, b2, b3);
    }
    {
        uint32_t off = base + (uint32_t)(6 * 8) * 2;
        uint32_t b0, b1;
        ldsm_x2t(b0, b1, bH + off);
        mma16816(acc[6], ah0, ah1, ah2, ah3, b0, b1);
        mma16816(acc[6], al0, al1, al2, al3, b0, b1);
        ldsm_x2t(b0, b1, bL + off);
        mma16816(acc[6], ah0, ah1, ah2, ah3, b0, b1);
    }
}

// ---------------- conversions ----------------
__global__ void k_splitX(const float* __restrict__ src)
{
    int i = blockIdx.x * 256 + threadIdx.x;
    if (i >= BS*TRS) return;
    int col = i % XW;
    int row = i / XW;
    float v = (col < HD) ? src[(size_t)row * HD + col] : 0.f;
    __nv_bfloat16 h = __float2bfloat16(v);
    g_Xh[i] = h;
    g_Xl[i] = __float2bfloat16(v - __bfloat162float(h));
}

__global__ void k_splitW(const float* __restrict__ wvs)
{
    int i = blockIdx.x * 256 + threadIdx.x;
    if (i >= 70*HD*WW) return;
    int col = i % WW;
    int row = i / WW;
    float v = (col < HD) ? wvs[(size_t)row * HD + col] : 0.f;
    __nv_bfloat16 h = __float2bfloat16(v);
    g_Wh[i] = h;
    g_Wl[i] = __float2bfloat16(v - __bfloat162float(h));
}

// ---------------- Sq = S @ wq_w^T + wq_b ----------------
__global__ void k_sq(const float* __restrict__ S, const float* __restrict__ wqw,
                     const float* __restrict__ wqb)
{
    int lane = threadIdx.x & 31;
    int gw = blockIdx.x * 8 + (threadIdx.x >> 5);
    if (gw >= BS*HD) return;
    int b = gw / HD, h = gw % HD;
    const float* sp = S + (size_t)b * SDIM;
    const float* wp = wqw + (size_t)h * SDIM;
    float acc = 0.f;
    for (int k = lane * 4; k < SDIM; k += 128) {
        float4 s4 = *(const float4*)(sp + k);
        float4 w4 = *(const float4*)(wp + k);
        acc += s4.x*w4.x + s4.y*w4.y + s4.z*w4.z + s4.w*w4.w;
    }
    #pragma unroll
    for (int o = 16; o > 0; o >>= 1) acc += __shfl_down_sync(0xffffffffu, acc, o);
    if (lane == 0) g_Sq[b*HD + h] = acc + wqb[h];
}

// ---------------- tensor-core Y GEMM (4-stage K16 via dynamic smem, wait<2>) ----------------
__global__ __launch_bounds__(256) void k_ygemm_tc(int mode, const float* __restrict__ uni,
                                                  const float* __restrict__ start,
                                                  const float* __restrict__ trans)
{
    extern __shared__ char dsm[];
    __nv_bfloat16 (*sAh)[64][24]  = (__nv_bfloat16(*)[64][24])(dsm);
    __nv_bfloat16 (*sAl)[64][24]  = (__nv_bfloat16(*)[64][24])(dsm + YG_AL_OFF);
    __nv_bfloat16 (*sBh)[16][120] = (__nv_bfloat16(*)[16][120])(dsm + YG_BH_OFF);
    __nv_bfloat16 (*sBl)[16][120] = (__nv_bfloat16(*)[16][120])(dsm + YG_BL_OFF);

    int r = blockIdx.x, b = blockIdx.y, z = blockIdx.z;
    int m0 = (z == 3) ? 136 : z * 64;

    const __nv_bfloat16 *Ah, *Al, *Wh, *Wl;
    if (mode == 0) {
        Ah = g_Xh + (size_t)b * TRS;  Al = g_Xl + (size_t)b * TRS;
        Wh = g_Wh + (size_t)r * HD * WW;  Wl = g_Wl + (size_t)r * HD * WW;
    } else {
        Ah = g_Trh + (size_t)(b*NH + r) * TRS;  Al = g_Trl + (size_t)(b*NH + r) * TRS;
        Wh = g_Wh + (size_t)(35 + r) * HD * WW;  Wl = g_Wl + (size_t)(35 + r) * HD * WW;
    }
    float cs = uni[b*NH + r];
    __nv_bfloat16* Oh = g_Yh + (size_t)(b*NH + r) * NN * YW;
    __nv_bfloat16* Ol = g_Yl + (size_t)(b*NH + r) * NN * YW;

    int tid = threadIdx.x, lane = tid & 31, wid = tid >> 5;
    int wm = wid & 3, wn = wid >> 2;

    {
        int st = tid >> 6;
        int rem = tid & 63;
        int arr = rem >> 5, row = (rem >> 1) & 15, sg = rem & 1;
        __nv_bfloat16* p = arr ? &sBl[st][row][104 + sg*8] : &sBh[st][row][104 + sg*8];
        *(uint4*)p = make_uint4(0u,0u,0u,0u);
    }

    float acc[7][4];
    #pragma unroll
    for (int f = 0; f < 7; ++f)
        #pragma unroll
        for (int q = 0; q < 4; ++q) acc[f][q] = 0.f;

    uint32_t aHBase = smem_u32(&sAh[0][wm*16 + (lane & 15)][(lane >> 4) * 8]);
    uint32_t aLBase = smem_u32(&sAl[0][wm*16 + (lane & 15)][(lane >> 4) * 8]);
    uint32_t bHBase = smem_u32(&sBh[0][lane & 15][(lane >> 4) * 8]);
    uint32_t bLBase = smem_u32(&sBl[0][lane & 15][(lane >> 4) * 8]);

    issueA16(Ah, Al, m0, 0, tid, sAh[0], sAl[0]);
    issueB16(Wh, Wl, 0, HD, tid, sBh[0], sBl[0]);
    cp_commit();
    issueA16(Ah, Al, m0, 16, tid, sAh[1], sAl[1]);
    issueB16(Wh, Wl, 16, HD, tid, sBh[1], sBl[1]);
    cp_commit();
    issueA16(Ah, Al, m0, 32, tid, sAh[2], sAl[2]);
    issueB16(Wh, Wl, 32, HD, tid, sBh[2], sBl[2]);
    cp_commit();

    #pragma unroll 1
    for (int c = 0; c < 7; ++c) {
        cp_wait_group<2>();
        __syncthreads();
        int nc = c + 3;
        if (nc < 7) {
            int st = nc & 3;
            issueA16(Ah, Al, m0, nc * 16, tid, sAh[st], sAl[st]);
            issueB16(Wh, Wl, nc * 16, HD, tid, sBh[st], sBl[st]);
        }
        cp_commit();
        int s = c & 3;
        compute_tile3(acc, aHBase + s*YG_A_STRIDE, aLBase + s*YG_A_STRIDE,
                      bHBase + s*YG_B_STRIDE, bLBase + s*YG_B_STRIDE, wn);
    }

    int g = lane >> 2, tg = lane & 3;
    #pragma unroll
    for (int f = 0; f < 7; ++f) {
        int c = wn*56 + f*8 + tg*2;
        if (c + 1 >= YW) continue;
        #pragma unroll
        for (int h2 = 0; h2 < 2; ++h2) {
            int row = m0 + wm*16 + g + h2*8;
            if (row >= NN) continue;
            float v0, v1;
            if (c <= 98) {
                float sc = cs * (mode == 0 ? start[b*NN + row] : 1.f);
                v0 = acc[f][2*h2] * sc;
                v1 = acc[f][2*h2 + 1] * sc;
            } else if (c == HD) {
                float dv;
                if (mode == 0) {
                    dv = cs * start[b*NN + row];
                } else {
                    float a = 0.f;
                    #pragma unroll 2
                    for (int rr = 0; rr < NH; ++rr)
                        a += g_D[(b*NH + rr)*NN + row] * trans[(b*NH + rr)*NH + r];
                    dv = cs * a;
                }
                v0 = dv; v1 = 0.f;
            } else {
                v0 = 0.f; v1 = 0.f;
            }
            __nv_bfloat16 h0 = __float2bfloat16(v0);
            __nv_bfloat16 h1 = __float2bfloat16(v1);
            __nv_bfloat162 hh; hh.x = h0; hh.y = h1;
            __nv_bfloat162 ll;
            ll.x = __float2bfloat16(v0 - __bfloat162float(h0));
            ll.y = __float2bfloat16(v1 - __bfloat162float(h1));
            size_t o = (size_t)row * YW + c;
            *(__nv_bfloat162*)(Oh + o) = hh;
            *(__nv_bfloat162*)(Ol + o) = ll;
        }
    }
}

// ---------------- t=0 A-GEMM (4-stage K16, wait<2>, static smem): Zh0 = A @ [Y0|dvec0] ----------------
__global__ __launch_bounds__(256) void k_agemm_tc(const float* __restrict__ A)
{
    int r = blockIdx.x, b = blockIdx.y, z = blockIdx.z;
    int m0 = (z == 3) ? 136 : z * 64;

    const float* Ap = A + (size_t)(b*NH + r) * NN * NN;
    const __nv_bfloat16* Yh = g_Yh + (size_t)(b*NH + r) * NN * YW;
    const __nv_bfloat16* Yl = g_Yl + (size_t)(b*NH + r) * NN * YW;
    float* Zb = g_Zh + (size_t)(b*NH + r) * NRH;
    float* Db = g_D + (b*NH + r) * NN;

    __shared__ __align__(16) __nv_bfloat16 sA[4][64][24];
    __shared__ __align__(16) __nv_bfloat16 sBh[4][16][120];
    __shared__ __align__(16) __nv_bfloat16 sBl[4][16][120];

    int tid = threadIdx.x, lane = tid & 31, wid = tid >> 5;
    int wm = wid & 3, wn = wid >> 2;

    {
        int st = tid >> 6;
        int rem = tid & 63;
        int arr = rem >> 5, row = (rem >> 1) & 15, sg = rem & 1;
        __nv_bfloat16* p = arr ? &sBl[st][row][104 + sg*8] : &sBh[st][row][104 + sg*8];
        *(uint4*)p = make_uint4(0u,0u,0u,0u);
    }

    float acc[7][4];
    #pragma unroll
    for (int f = 0; f < 7; ++f)
        #pragma unroll
        for (int q = 0; q < 4; ++q) acc[f][q] = 0.f;

    uint32_t aBase = smem_u32(&sA[0][wm*16 + (lane & 15)][(lane >> 4) * 8]);
    uint32_t bHBase = smem_u32(&sBh[0][lane & 15][(lane >> 4) * 8]);
    uint32_t bLBase = smem_u32(&sBl[0][lane & 15][(lane >> 4) * 8]);

    float4 av = loadA16(Ap, m0, 0, tid);
    issueB16(Yh, Yl, 0, NN, tid, sBh[0], sBl[0]);
    cp_commit();
    stsA16(av, sA[0], tid);
    av = loadA16(Ap, m0, 16, tid);
    issueB16(Yh, Yl, 16, NN, tid, sBh[1], sBl[1]);
    cp_commit();
    stsA16(av, sA[1], tid);
    av = loadA16(Ap, m0, 32, tid);
    issueB16(Yh, Yl, 32, NN, tid, sBh[2], sBl[2]);
    cp_commit();
    stsA16(av, sA[2], tid);
    av = loadA16(Ap, m0, 48, tid);

    #pragma unroll 1
    for (int i = 0; i < 13; ++i) {
        cp_wait_group<2>();
        __syncthreads();
        int nc = i + 3;
        if (nc < 13)
            issueB16(Yh, Yl, nc * 16, NN, tid, sBh[nc & 3], sBl[nc & 3]);
        cp_commit();
        int s = i & 3;
        compute_tile(acc, aBase + s*3072, bHBase + s*3840, bLBase + s*3840, wn);
        if (nc < 13) {
            stsA16(av, sA[nc & 3], tid);
            if (nc + 1 < 13) av = loadA16(Ap, m0, (nc + 1) * 16, tid);
        }
    }

    int g = lane >> 2, tg = lane & 3;
    #pragma unroll
    for (int f = 0; f < 7; ++f) {
        int c = wn*56 + f*8 + tg*2;
        #pragma unroll
        for (int h2 = 0; h2 < 2; ++h2) {
            int row = m0 + wm*16 + g + h2*8;
            if (row >= NN) continue;
            if (c <= 98)
                *(float2*)(Zb + row*HD + c) = make_float2(acc[f][2*h2], acc[f][2*h2 + 1]);
            else if (c == HD)
                Db[row] = acc[f][2*h2];
        }
    }
}

// ---------------- zero Zt1/Dt1 accumulators ----------------
__global__ void k_zero1()
{
    int i = blockIdx.x * 256 + threadIdx.x;
    if (i < BS*NRH) g_Zt[(size_t)BS*NRH + i] = 0.f;
    if (i < BS*NN)  g_Dt[BS*NN + i] = 0.f;
}

// ---------------- t=1 grouped A-GEMM (4-stage K16, wait<2>): atomic partials, 4 heads/CTA ----------------
__global__ __launch_bounds__(256) void k_agemm1_tc(const float* __restrict__ A,
                                                   const float* __restrict__ endv)
{
    int z = blockIdx.x, b = blockIdx.y, rg = blockIdx.z;
    int m0 = (z == 3) ? 136 : z * 64;
    int rbase = rg * 4;
    int nr = min(4, NH - rbase);
    const int NCH = nr * 13;

    __shared__ __align__(16) __nv_bfloat16 sA[4][64][24];
    __shared__ __align__(16) __nv_bfloat16 sBh[4][16][120];
    __shared__ __align__(16) __nv_bfloat16 sBl[4][16][120];

    int tid = threadIdx.x, lane = tid & 31, wid = tid >> 5;
    int wm = wid & 3, wn = wid >> 2;

    {
        int st = tid >> 6;
        int rem = tid & 63;
        int arr = rem >> 5, row = (rem >> 1) & 15, sg = rem & 1;
        __nv_bfloat16* p = arr ? &sBl[st][row][104 + sg*8] : &sBh[st][row][104 + sg*8];
        *(uint4*)p = make_uint4(0u,0u,0u,0u);
    }

    float acc[7][4];
    #pragma unroll
    for (int f = 0; f < 7; ++f)
        #pragma unroll
        for (int q = 0; q < 4; ++q) acc[f][q] = 0.f;

    uint32_t aBase = smem_u32(&sA[0][wm*16 + (lane & 15)][(lane >> 4) * 8]);
    uint32_t bHBase = smem_u32(&sBh[0][lane & 15][(lane >> 4) * 8]);
    uint32_t bLBase = smem_u32(&sBl[0][lane & 15][(lane >> 4) * 8]);

    auto chunkPtrs = [&](int idx, const float*& Ap, const __nv_bfloat16*& Yh,
                         const __nv_bfloat16*& Yl, int& cn) {
        int rn = rbase + idx / 13; cn = idx % 13;
        Ap = A + (size_t)(b*NH + rn) * NN * NN;
        Yh = g_Yh + (size_t)(b*NH + rn) * NN * YW;
        Yl = g_Yl + (size_t)(b*NH + rn) * NN * YW;
    };

    const float* Ap; const __nv_bfloat16 *Yh, *Yl; int cn;
    chunkPtrs(0, Ap, Yh, Yl, cn);
    float4 av = loadA16(Ap, m0, 0, tid);
    issueB16(Yh, Yl, 0, NN, tid, sBh[0], sBl[0]);
    cp_commit();
    stsA16(av, sA[0], tid);
    chunkPtrs(1, Ap, Yh, Yl, cn);
    av = loadA16(Ap, m0, cn * 16, tid);
    issueB16(Yh, Yl, cn * 16, NN, tid, sBh[1], sBl[1]);
    cp_commit();
    stsA16(av, sA[1], tid);
    chunkPtrs(2, Ap, Yh, Yl, cn);
    av = loadA16(Ap, m0, cn * 16, tid);
    issueB16(Yh, Yl, cn * 16, NN, tid, sBh[2], sBl[2]);
    cp_commit();
    stsA16(av, sA[2], tid);
    chunkPtrs(3, Ap, Yh, Yl, cn);
    av = loadA16(Ap, m0, cn * 16, tid);

    #pragma unroll 1
    for (int i = 0; i < NCH; ++i) {
        cp_wait_group<2>();
        __syncthreads();
        int nc = i + 3;
        if (nc < NCH) {
            const float* Ap2; const __nv_bfloat16 *Yh2, *Yl2; int cn2;
            chunkPtrs(nc, Ap2, Yh2, Yl2, cn2);
            issueB16(Yh2, Yl2, cn2 * 16, NN, tid, sBh[nc & 3], sBl[nc & 3]);
        }
        cp_commit();
        int s = i & 3;
        compute_tile(acc, aBase + s*3072, bHBase + s*3840, bLBase + s*3840, wn);
        if (nc < NCH) {
            stsA16(av, sA[nc & 3], tid);
            if (nc + 1 < NCH) {
                chunkPtrs(nc + 1, Ap, Yh, Yl, cn);
                av = loadA16(Ap, m0, cn * 16, tid);
            }
        }
    }

    int rowlo = (z == 3) ? 192 : m0;
    int g = lane >> 2, tg = lane & 3;
    #pragma unroll
    for (int f = 0; f < 7; ++f) {
        int nb = wn*56 + f*8;
        #pragma unroll
        for (int q = 0; q < 4; ++q) {
            int row = m0 + wm*16 + g + (q >> 1) * 8;
            int col = nb + tg*2 + (q & 1);
            if (row >= rowlo && row < NN) {
                float e = endv[b*NN + row];
                if (col < HD)
                    atomicAdd(&g_Zt[(size_t)(BS + b) * NRH + row*HD + col], acc[f][q] * e);
                else if (col == HD)
                    atomicAdd(&g_Dt[BS*NN + b*NN + row], acc[f][q] * e);
            }
        }
    }
}

// ---------------- Dt0[b,i] = end * sum_r D0[b,r,i] ----------------
__global__ void k_dt(const float* __restrict__ endv)
{
    int idx = blockIdx.x * 256 + threadIdx.x;
    if (idx >= BS*NN) return;
    int b = idx / NN, i = idx - b*NN;
    float acc = 0.f;
    #pragma unroll 2
    for (int r = 0; r < NH; ++r) acc += g_D[(b*NH + r)*NN + i];
    g_Dt[idx] = acc * endv[idx];
}

// ---------------- fused trans-mix + r-sum over Zh0 (smem-staged, low-reg) ----------------
// block: 256 x-elements of batch b.  Phase1: stage Zh0[34][256] in smem.
// Phase2: per thread, 34 outputs in s-groups of 8 (max 8 accumulators live).
__global__ __launch_bounds__(256) void k_transsum(const float* __restrict__ trans)
{
    int b = blockIdx.y;
    int x0 = blockIdx.x * 256;
    int tid = threadIdx.x;
    int x = x0 + tid;

    __shared__ float ts[NH*NH];          // 4.6 KB
    __shared__ float sm[NH][257];        // 35 KB (pad 1 to dodge conflicts)

    for (int i = tid; i < NH*NH; i += 256) ts[i] = trans[b*NH*NH + i];

    const float* Zb = g_Zh + (size_t)b * NH * NRH;
    #pragma unroll 2
    for (int r = 0; r < NH; ++r)
        sm[r][tid] = (x < NRH) ? Zb[(size_t)r*NRH + x] : 0.f;
    __syncthreads();

    // r-sum
    {
        float sv = 0.f;
        #pragma unroll 2
        for (int r = 0; r < NH; ++r) sv += sm[r][tid];
        if (x < NRH) g_Zsum[(size_t)b * NRH + x] = sv;
    }

    if (x >= NRH) return;
    int j = x / HD, d = x - j*HD;
    size_t pp = (size_t)j * XW + d;
    bool pad = (d >= 96);

    // s-groups of 8 (last group = 2)
    #pragma unroll 1
    for (int s0 = 0; s0 < NH; s0 += 8) {
        int gs = min(8, NH - s0);
        float acc[8];
        #pragma unroll
        for (int g = 0; g < 8; ++g) acc[g] = 0.f;
        #pragma unroll 2
        for (int r = 0; r < NH; ++r) {
            float v = sm[r][tid];
            #pragma unroll
            for (int g = 0; g < 8; ++g)
                if (g < gs) acc[g] += v * ts[r*NH + s0 + g];
        }
        #pragma unroll
        for (int g = 0; g < 8; ++g) {
            if (g >= gs) break;
            int s = s0 + g;
            size_t ob = (size_t)(b*NH + s) * TRS;
            float v = acc[g];
            __nv_bfloat16 h = __float2bfloat16(v);
            g_Trh[ob + pp] = h;
            g_Trl[ob + pp] = __float2bfloat16(v - __bfloat162float(h));
            if (pad) { g_Trh[ob + pp + 4] = __float2bfloat16(0.f);
                       g_Trl[ob + pp + 4] = __float2bfloat16(0.f); }
        }
    }
}

// ---------------- Zt0 = rowscale(end) * (Zsum[b] @ Wpad)  grid (2, BS) ----------------
__global__ void k_zt0(const float* __restrict__ wvs, const float* __restrict__ endv)
{
    int mt = blockIdx.x;
    int b = blockIdx.y;
    const float* In = g_Zsum + (size_t)b * NRH;
    const float* W = wvs + (size_t)69 * (HD*HD);
    const float* rs = endv + b*NN;
    float* Out = g_Zt + (size_t)b * NRH;

    __shared__ float As[128][33];
    __shared__ float Bs[32][128];
    int tid = threadIdx.x;
    int tx = tid & 15, ty = tid >> 4;

    float acc[8][8];
    #pragma unroll
    for (int i = 0; i < 8; ++i)
        #pragma unroll
        for (int j = 0; j < 8; ++j) acc[i][j] = 0.f;

    for (int k0 = 0; k0 < HD; k0 += 32) {
        int klen = min(32, HD - k0);
        #pragma unroll
        for (int l = 0; l < 4; ++l) {
            int idx = tid + l*256;
            int row = idx >> 3;
            int c4 = (idx & 7) << 2;
            int grow = mt*128 + row;
            float4 v = make_float4(0.f,0.f,0.f,0.f);
            if (grow < NN && c4 < klen)
                v = *(const float4*)(In + (size_t)grow*HD + k0 + c4);
            As[row][c4+0] = v.x; As[row][c4+1] = v.y;
            As[row][c4+2] = v.z; As[row][c4+3] = v.w;
        }
        #pragma unroll
        for (int l = 0; l < 4; ++l) {
            int idx = tid + l*256;
            int kk = idx >> 5;
            int c4 = (idx & 31) << 2;
            float4 v = make_float4(0.f,0.f,0.f,0.f);
            if (kk < klen && c4 < HD)
                v = *(const float4*)(W + (size_t)(k0+kk)*HD + c4);
            *(float4*)&Bs[kk][c4] = v;
        }
        __syncthreads();
        #pragma unroll 4
        for (int kk = 0; kk < klen; ++kk) {
            float a[8];
            #pragma unroll
            for (int i = 0; i < 8; ++i) a[i] = As[ty*8 + i][kk];
            float4 b0 = *(float4*)&Bs[kk][tx*8];
            float4 b1 = *(float4*)&Bs[kk][tx*8 + 4];
            float bb[8] = {b0.x,b0.y,b0.z,b0.w,b1.x,b1.y,b1.z,b1.w};
            #pragma unroll
            for (int i = 0; i < 8; ++i)
                #pragma unroll
                for (int j = 0; j < 8; ++j)
                    acc[i][j] += a[i] * bb[j];
        }
        __syncthreads();
    }
    #pragma unroll
    for (int i = 0; i < 8; ++i) {
        int grow = mt*128 + ty*8 + i;
        if (grow < NN) {
            float sc = rs[grow];
            #pragma unroll
            for (int j = 0; j < 8; ++j) {
                int c = tx*8 + j;
                if (c < HD) Out[(size_t)grow*HD + c] = acc[i][j] * sc;
            }
        }
    }
}

// ---------------- epilogue ----------------
__global__ void k_out(float* __restrict__ out)
{
    int bn = blockIdx.x;
    int b = bn / NN, n = bn - b*NN;
    int tid = threadIdx.x;
    __shared__ float red[128];

    float z[2], dt[2];
    #pragma unroll
    for (int t = 0; t < 2; ++t) {
        float zv = 0.f;
        if (tid < HD) {
            float dd = g_Dt[t*BS*NN + b*NN + n];
            zv = g_Zt[(size_t)(t*BS + b) * NRH + n*HD + tid] / (dd + EPSV);
        }
        z[t] = zv;
        red[tid] = (tid < HD) ? g_Sq[b*HD + tid] * zv : 0.f;
        __syncthreads();
        for (int s = 64; s > 0; s >>= 1) {
            if (tid < s) red[tid] += red[tid + s];
            __syncthreads();
        }
        dt[t] = red[0] * 0.1f;
        __syncthreads();
    }
    float m = fmaxf(dt[0], dt[1]);
    float e0 = expf(dt[0] - m), e1 = expf(dt[1] - m);
    float inv = 1.f / (e0 + e1);
    if (tid < HD)
        out[(size_t)bn * HD + tid] = (e0 * z[0] + e1 * z[1]) * inv;
}

// ---------------- launch (multi-stream, graph-capturable fork/join) ----------------
extern "C" void kernel_launch(void* const* d_in, const int* in_sizes, int n_in,
                              void* d_out, int out_size)
{
    (void)in_sizes; (void)n_in; (void)out_size;
    const float* X     = (const float*)d_in[0];
    const float* A     = (const float*)d_in[1];
    const float* start = (const float*)d_in[2];
    const float* endv  = (const float*)d_in[3];
    const float* uni   = (const float*)d_in[4];
    const float* trans = (const float*)d_in[5];
    const float* S     = (const float*)d_in[6];
    const float* wvs   = (const float*)d_in[7];
    const float* wqw   = (const float*)d_in[8];
    const float* wqb   = (const float*)d_in[9];
    float* out = (float*)d_out;

    static cudaStream_t s1, s2, s3;
    static cudaEvent_t e0, e1, e2, e3, e4, e5, e6;
    static bool init = false;
    if (!init) {
        cudaStreamCreateWithFlags(&s1, cudaStreamNonBlocking);
        cudaStreamCreateWithFlags(&s2, cudaStreamNonBlocking);
        cudaStreamCreateWithFlags(&s3, cudaStreamNonBlocking);
        cudaEventCreateWithFlags(&e0, cudaEventDisableTiming);
        cudaEventCreateWithFlags(&e1, cudaEventDisableTiming);
        cudaEventCreateWithFlags(&e2, cudaEventDisableTiming);
        cudaEventCreateWithFlags(&e3, cudaEventDisableTiming);
        cudaEventCreateWithFlags(&e4, cudaEventDisableTiming);
        cudaEventCreateWithFlags(&e5, cudaEventDisableTiming);
        cudaEventCreateWithFlags(&e6, cudaEventDisableTiming);
        cudaFuncSetAttribute((const void*)k_ygemm_tc,
                             cudaFuncAttributeMaxDynamicSharedMemorySize, YG_SMEM);
        init = true;
    }

    cudaEventRecord(e0, 0);
    cudaStreamWaitEvent(s1, e0, 0);
    cudaStreamWaitEvent(s2, e0, 0);
    cudaStreamWaitEvent(s3, e0, 0);

    k_sq<<<(BS*HD + 7) / 8, 256, 0, s1>>>(S, wqw, wqb);
    k_splitW<<<(70*HD*WW + 255)/256, 256, 0, s2>>>(wvs);
    k_zero1<<<(BS*NRH + 255)/256, 256, 0, s3>>>();
    k_splitX<<<(BS*TRS + 255)/256, 256>>>(X);

    cudaEventRecord(e1, s2);
    cudaStreamWaitEvent(0, e1, 0);

    dim3 gg(NH, BS, 4);
    k_ygemm_tc<<<gg, 256, YG_SMEM>>>(0, uni, start, trans);
    k_agemm_tc<<<gg, 256>>>(A);

    cudaEventRecord(e2, 0);
    cudaStreamWaitEvent(s1, e2, 0);
    k_dt<<<(BS*NN + 255)/256, 256, 0, s1>>>(endv);

    k_transsum<<<dim3((NRH + 255)/256, BS), 256>>>(trans);

    cudaEventRecord(e3, 0);
    cudaStreamWaitEvent(s2, e3, 0);
    k_zt0<<<dim3(2, BS), 256, 0, s2>>>(wvs, endv);

    k_ygemm_tc<<<gg, 256, YG_SMEM>>>(1, uni, start, trans);
    cudaEventRecord(e4, s3);
    cudaStreamWaitEvent(0, e4, 0);
    k_agemm1_tc<<<dim3(4, BS, 9), 256>>>(A, endv);

    cudaEventRecord(e5, s1);
    cudaStreamWaitEvent(0, e5, 0);
    cudaEventRecord(e6, s2);
    cudaStreamWaitEvent(0, e6, 0);
    k_out<<<BS*NN, 128>>>(out);
}

// round 17
// speedup vs baseline: 1.0957x; 1.0063x over previous
#include <cuda_runtime.h>
#include <cuda_bf16.h>
#include <cstdint>

#define BS 32
#define NN 200
#define HD 100
#define NH 34
#define SDIM 1024
#define NRH (NN*HD)   // 20000
#define YW 104
#define WW 104
#define XW 104
#define TRS (NN*XW)   // 20800
#define EPSV 1e-20f

// ygemm dynamic smem layout (4 stages)
#define YG_A_STRIDE 3072
#define YG_B_STRIDE 3840
#define YG_AL_OFF   12288
#define YG_BH_OFF   24576
#define YG_BL_OFF   39936
#define YG_SMEM     55296

// ---------------- scratch ----------------
__device__ __align__(16) __nv_bfloat16 g_Yh[(size_t)BS*NH*NN*YW];
__device__ __align__(16) __nv_bfloat16 g_Yl[(size_t)BS*NH*NN*YW];
__device__ __align__(16) __nv_bfloat16 g_Trh[(size_t)BS*NH*TRS];
__device__ __align__(16) __nv_bfloat16 g_Trl[(size_t)BS*NH*TRS];
__device__ __align__(16) __nv_bfloat16 g_Xh[BS*TRS];
__device__ __align__(16) __nv_bfloat16 g_Xl[BS*TRS];
__device__ __align__(16) __nv_bfloat16 g_Wh[70*HD*WW];
__device__ __align__(16) __nv_bfloat16 g_Wl[70*HD*WW];
__device__ float g_Zh[(size_t)BS*NH*NRH];
__device__ float g_Zsum[BS*NRH];
__device__ float g_D[BS*NH*NN];
__device__ float g_Zt[2*BS*NRH];
__device__ float g_Dt[2*BS*NN];
__device__ float g_Sq[BS*HD];

// ---------------- PTX helpers ----------------
__device__ __forceinline__ uint32_t smem_u32(const void* p) {
    return (uint32_t)__cvta_generic_to_shared(p);
}
__device__ __forceinline__ void ldsm_x4(uint32_t& r0, uint32_t& r1, uint32_t& r2, uint32_t& r3, uint32_t addr) {
    asm volatile("ldmatrix.sync.aligned.m8n8.x4.shared.b16 {%0,%1,%2,%3},[%4];"
                 : "=r"(r0), "=r"(r1), "=r"(r2), "=r"(r3) : "r"(addr));
}
__device__ __forceinline__ void ldsm_x4t(uint32_t& r0, uint32_t& r1, uint32_t& r2, uint32_t& r3, uint32_t addr) {
    asm volatile("ldmatrix.sync.aligned.m8n8.x4.trans.shared.b16 {%0,%1,%2,%3},[%4];"
                 : "=r"(r0), "=r"(r1), "=r"(r2), "=r"(r3) : "r"(addr));
}
__device__ __forceinline__ void ldsm_x2t(uint32_t& r0, uint32_t& r1, uint32_t addr) {
    asm volatile("ldmatrix.sync.aligned.m8n8.x2.trans.shared.b16 {%0,%1},[%2];"
                 : "=r"(r0), "=r"(r1) : "r"(addr));
}
__device__ __forceinline__ void mma16816(float* c, uint32_t a0, uint32_t a1, uint32_t a2, uint32_t a3,
                                         uint32_t b0, uint32_t b1) {
    asm volatile("mma.sync.aligned.m16n8k16.row.col.f32.bf16.bf16.f32 "
                 "{%0,%1,%2,%3},{%4,%5,%6,%7},{%8,%9},{%0,%1,%2,%3};"
                 : "+f"(c[0]), "+f"(c[1]), "+f"(c[2]), "+f"(c[3])
                 : "r"(a0), "r"(a1), "r"(a2), "r"(a3), "r"(b0), "r"(b1));
}
__device__ __forceinline__ void cp16(uint32_t dst, const void* src) {
    asm volatile("cp.async.cg.shared.global [%0], [%1], 16;" :: "r"(dst), "l"(src));
}
__device__ __forceinline__ void cp_commit() { asm volatile("cp.async.commit_group;"); }
template<int N> __device__ __forceinline__ void cp_wait_group() {
    asm volatile("cp.async.wait_group %0;" :: "n"(N));
}

// ---------------- pipelined-GEMM building blocks ----------------
__device__ __forceinline__ float4 loadA16(const float* __restrict__ Ap, int m0, int k0, int tid)
{
    int row = tid >> 2, kp = (tid & 3) * 4;
    int gk = k0 + kp;
    float4 v = make_float4(0.f, 0.f, 0.f, 0.f);
    if (gk + 3 < NN) v = *(const float4*)(Ap + (size_t)(m0 + row) * NN + gk);
    return v;
}
__device__ __forceinline__ void stsA16(float4 v, __nv_bfloat16 (*sA)[24], int tid)
{
    int row = tid >> 2, kp = (tid & 3) * 4;
    __nv_bfloat162 h0 = __floats2bfloat162_rn(v.x, v.y);
    __nv_bfloat162 h1 = __floats2bfloat162_rn(v.z, v.w);
    uint2 p;
    p.x = *reinterpret_cast<uint32_t*>(&h0);
    p.y = *reinterpret_cast<uint32_t*>(&h1);
    *(uint2*)&sA[row][kp] = p;
}
__device__ __forceinline__ void issueB16(const __nv_bfloat16* __restrict__ Bh,
                                         const __nv_bfloat16* __restrict__ Bl,
                                         int k0, int klim, int tid,
                                         __nv_bfloat16 (*sH)[120], __nv_bfloat16 (*sL)[120])
{
    if (tid < 208) {
        int row = tid / 13, cc = tid - row * 13;
        int gj = k0 + row;
        __nv_bfloat16* dh = &sH[row][cc * 8];
        __nv_bfloat16* dl = &sL[row][cc * 8];
        if (gj < klim) {
            cp16(smem_u32(dh), Bh + (size_t)gj * 104 + cc * 8);
            cp16(smem_u32(dl), Bl + (size_t)gj * 104 + cc * 8);
        } else {
            uint4 z = make_uint4(0u, 0u, 0u, 0u);
            *(uint4*)dh = z; *(uint4*)dl = z;
        }
    }
}
__device__ __forceinline__ void issueA16(const __nv_bfloat16* __restrict__ Ah,
                                         const __nv_bfloat16* __restrict__ Al,
                                         int m0, int k0, int tid,
                                         __nv_bfloat16 (*sH)[24], __nv_bfloat16 (*sL)[24])
{
    int row = tid >> 2, q = tid & 3;
    int seg = q & 1;
    int lo = q >> 1;
    int gk = k0 + seg * 8;
    const __nv_bfloat16* src = (lo ? Al : Ah) + (size_t)(m0 + row) * XW + gk;
    __nv_bfloat16* dst = lo ? &sL[row][seg*8] : &sH[row][seg*8];
    if (gk < XW) cp16(smem_u32(dst), src);
    else *(uint4*)dst = make_uint4(0u,0u,0u,0u);
}
__device__ __forceinline__ void compute_tile(float (*acc)[4], uint32_t aAddr,
                                             uint32_t bH, uint32_t bL, int wn)
{
    uint32_t a0, a1, a2, a3;
    ldsm_x4(a0, a1, a2, a3, aAddr);
    uint32_t base = (uint32_t)(wn * 56) * 2;
    #pragma unroll
    for (int p = 0; p < 3; ++p) {
        uint32_t off = base + (uint32_t)(p * 16) * 2;
        uint32_t b0, b1, b2, b3;
        ldsm_x4t(b0, b1, b2, b3, bH + off);
        mma16816(acc[2*p],   a0, a1, a2, a3, b0, b1);
        mma16816(acc[2*p+1], a0, a1, a2, a3, b2, b3);
        ldsm_x4t(b0, b1, b2, b3, bL + off);
        mma16816(acc[2*p],   a0, a1, a2, a3, b0, b1);
        mma16816(acc[2*p+1], a0, a1, a2, a3, b2, b3);
    }
    {
        uint32_t off = base + (uint32_t)(6 * 8) * 2;
        uint32_t b0, b1;
        ldsm_x2t(b0, b1, bH + off);
        mma16816(acc[6], a0, a1, a2, a3, b0, b1);
        ldsm_x2t(b0, b1, bL + off);
        mma16816(acc[6], a0, a1, a2, a3, b0, b1);
    }
}
__device__ __forceinline__ void compute_tile3(float (*acc)[4], uint32_t aH, uint32_t aL,
                                              uint32_t bH, uint32_t bL, int wn)
{
    uint32_t ah0, ah1, ah2, ah3, al0, al1, al2, al3;
    ldsm_x4(ah0, ah1, ah2, ah3, aH);
    ldsm_x4(al0, al1, al2, al3, aL);
    uint32_t base = (uint32_t)(wn * 56) * 2;
    #pragma unroll
    for (int p = 0; p < 3; ++p) {
        uint32_t off = base + (uint32_t)(p * 16) * 2;
        uint32_t b0, b1, b2, b3;
        ldsm_x4t(b0, b1, b2, b3, bH + off);
        mma16816(acc[2*p],   ah0, ah1, ah2, ah3, b0, b1);
        mma16816(acc[2*p],   al0, al1, al2, al3, b0, b1);
        mma16816(acc[2*p+1], ah0, ah1, ah2, ah3, b2, b3);
        mma16816(acc[2*p+1], al0, al1, al2, al3, b2, b3);
        ldsm_x4t(b0, b1, b2, b3, bL + off);
        mma16816(acc[2*p],   ah0, ah1, ah2, ah3, b0, b1);
        mma16816(acc[2*p+1], ah0, ah1, ah2, ah3, b2, b3);
    }
    {
        uint32_t off = base + (uint32_t)(6 * 8) * 2;
        uint32_t b0, b1;
        ldsm_x2t(b0, b1, bH + off);
        mma16816(acc[6], ah0, ah1, ah2, ah3, b0, b1);
        mma16816(acc[6], al0, al1, al2, al3, b0, b1);
        ldsm_x2t(b0, b1, bL + off);
        mma16816(acc[6], ah0, ah1, ah2, ah3, b0, b1);
    }
}

// ---------------- conversions ----------------
__global__ void k_splitX(const float* __restrict__ src)
{
    int i = blockIdx.x * 256 + threadIdx.x;
    if (i >= BS*TRS) return;
    int col = i % XW;
    int row = i / XW;
    float v = (col < HD) ? src[(size_t)row * HD + col] : 0.f;
    __nv_bfloat16 h = __float2bfloat16(v);
    g_Xh[i] = h;
    g_Xl[i] = __float2bfloat16(v - __bfloat162float(h));
}

__global__ void k_splitW(const float* __restrict__ wvs)
{
    int i = blockIdx.x * 256 + threadIdx.x;
    if (i >= 70*HD*WW) return;
    int col = i % WW;
    int row = i / WW;
    float v = (col < HD) ? wvs[(size_t)row * HD + col] : 0.f;
    __nv_bfloat16 h = __float2bfloat16(v);
    g_Wh[i] = h;
    g_Wl[i] = __float2bfloat16(v - __bfloat162float(h));
}

// ---------------- Sq = S @ wq_w^T + wq_b ----------------
__global__ void k_sq(const float* __restrict__ S, const float* __restrict__ wqw,
                     const float* __restrict__ wqb)
{
    int lane = threadIdx.x & 31;
    int gw = blockIdx.x * 8 + (threadIdx.x >> 5);
    if (gw >= BS*HD) return;
    int b = gw / HD, h = gw % HD;
    const float* sp = S + (size_t)b * SDIM;
    const float* wp = wqw + (size_t)h * SDIM;
    float acc = 0.f;
    for (int k = lane * 4; k < SDIM; k += 128) {
        float4 s4 = *(const float4*)(sp + k);
        float4 w4 = *(const float4*)(wp + k);
        acc += s4.x*w4.x + s4.y*w4.y + s4.z*w4.z + s4.w*w4.w;
    }
    #pragma unroll
    for (int o = 16; o > 0; o >>= 1) acc += __shfl_down_sync(0xffffffffu, acc, o);
    if (lane == 0) g_Sq[b*HD + h] = acc + wqb[h];
}

// ---------------- tensor-core Y GEMM (4-stage K16 via dynamic smem, wait<2>) ----------------
__global__ __launch_bounds__(256) void k_ygemm_tc(int mode, const float* __restrict__ uni,
                                                  const float* __restrict__ start,
                                                  const float* __restrict__ trans)
{
    extern __shared__ char dsm[];
    __nv_bfloat16 (*sAh)[64][24]  = (__nv_bfloat16(*)[64][24])(dsm);
    __nv_bfloat16 (*sAl)[64][24]  = (__nv_bfloat16(*)[64][24])(dsm + YG_AL_OFF);
    __nv_bfloat16 (*sBh)[16][120] = (__nv_bfloat16(*)[16][120])(dsm + YG_BH_OFF);
    __nv_bfloat16 (*sBl)[16][120] = (__nv_bfloat16(*)[16][120])(dsm + YG_BL_OFF);

    int r = blockIdx.x, b = blockIdx.y, z = blockIdx.z;
    int m0 = (z == 3) ? 136 : z * 64;

    const __nv_bfloat16 *Ah, *Al, *Wh, *Wl;
    if (mode == 0) {
        Ah = g_Xh + (size_t)b * TRS;  Al = g_Xl + (size_t)b * TRS;
        Wh = g_Wh + (size_t)r * HD * WW;  Wl = g_Wl + (size_t)r * HD * WW;
    } else {
        Ah = g_Trh + (size_t)(b*NH + r) * TRS;  Al = g_Trl + (size_t)(b*NH + r) * TRS;
        Wh = g_Wh + (size_t)(35 + r) * HD * WW;  Wl = g_Wl + (size_t)(35 + r) * HD * WW;
    }
    float cs = uni[b*NH + r];
    __nv_bfloat16* Oh = g_Yh + (size_t)(b*NH + r) * NN * YW;
    __nv_bfloat16* Ol = g_Yl + (size_t)(b*NH + r) * NN * YW;

    int tid = threadIdx.x, lane = tid & 31, wid = tid >> 5;
    int wm = wid & 3, wn = wid >> 2;

    {
        int st = tid >> 6;
        int rem = tid & 63;
        int arr = rem >> 5, row = (rem >> 1) & 15, sg = rem & 1;
        __nv_bfloat16* p = arr ? &sBl[st][row][104 + sg*8] : &sBh[st][row][104 + sg*8];
        *(uint4*)p = make_uint4(0u,0u,0u,0u);
    }

    float acc[7][4];
    #pragma unroll
    for (int f = 0; f < 7; ++f)
        #pragma unroll
        for (int q = 0; q < 4; ++q) acc[f][q] = 0.f;

    uint32_t aHBase = smem_u32(&sAh[0][wm*16 + (lane & 15)][(lane >> 4) * 8]);
    uint32_t aLBase = smem_u32(&sAl[0][wm*16 + (lane & 15)][(lane >> 4) * 8]);
    uint32_t bHBase = smem_u32(&sBh[0][lane & 15][(lane >> 4) * 8]);
    uint32_t bLBase = smem_u32(&sBl[0][lane & 15][(lane >> 4) * 8]);

    issueA16(Ah, Al, m0, 0, tid, sAh[0], sAl[0]);
    issueB16(Wh, Wl, 0, HD, tid, sBh[0], sBl[0]);
    cp_commit();
    issueA16(Ah, Al, m0, 16, tid, sAh[1], sAl[1]);
    issueB16(Wh, Wl, 16, HD, tid, sBh[1], sBl[1]);
    cp_commit();
    issueA16(Ah, Al, m0, 32, tid, sAh[2], sAl[2]);
    issueB16(Wh, Wl, 32, HD, tid, sBh[2], sBl[2]);
    cp_commit();

    #pragma unroll 1
    for (int c = 0; c < 7; ++c) {
        cp_wait_group<2>();
        __syncthreads();
        int nc = c + 3;
        if (nc < 7) {
            int st = nc & 3;
            issueA16(Ah, Al, m0, nc * 16, tid, sAh[st], sAl[st]);
            issueB16(Wh, Wl, nc * 16, HD, tid, sBh[st], sBl[st]);
        }
        cp_commit();
        int s = c & 3;
        compute_tile3(acc, aHBase + s*YG_A_STRIDE, aLBase + s*YG_A_STRIDE,
                      bHBase + s*YG_B_STRIDE, bLBase + s*YG_B_STRIDE, wn);
    }

    int g = lane >> 2, tg = lane & 3;
    #pragma unroll
    for (int f = 0; f < 7; ++f) {
        int c = wn*56 + f*8 + tg*2;
        if (c + 1 >= YW) continue;
        #pragma unroll
        for (int h2 = 0; h2 < 2; ++h2) {
            int row = m0 + wm*16 + g + h2*8;
            if (row >= NN) continue;
            float v0, v1;
            if (c <= 98) {
                float sc = cs * (mode == 0 ? start[b*NN + row] : 1.f);
                v0 = acc[f][2*h2] * sc;
                v1 = acc[f][2*h2 + 1] * sc;
            } else if (c == HD) {
                float dv;
                if (mode == 0) {
                    dv = cs * start[b*NN + row];
                } else {
                    float a = 0.f;
                    #pragma unroll 2
                    for (int rr = 0; rr < NH; ++rr)
                        a += g_D[(b*NH + rr)*NN + row] * trans[(b*NH + rr)*NH + r];
                    dv = cs * a;
                }
                v0 = dv; v1 = 0.f;
            } else {
                v0 = 0.f; v1 = 0.f;
            }
            __nv_bfloat16 h0 = __float2bfloat16(v0);
            __nv_bfloat16 h1 = __float2bfloat16(v1);
            __nv_bfloat162 hh; hh.x = h0; hh.y = h1;
            __nv_bfloat162 ll;
            ll.x = __float2bfloat16(v0 - __bfloat162float(h0));
            ll.y = __float2bfloat16(v1 - __bfloat162float(h1));
            size_t o = (size_t)row * YW + c;
            *(__nv_bfloat162*)(Oh + o) = hh;
            *(__nv_bfloat162*)(Ol + o) = ll;
        }
    }
}

// ---------------- t=0 A-GEMM (4-stage K16, wait<2>, static smem): Zh0 = A @ [Y0|dvec0] ----------------
__global__ __launch_bounds__(256) void k_agemm_tc(const float* __restrict__ A)
{
    int r = blockIdx.x, b = blockIdx.y, z = blockIdx.z;
    int m0 = (z == 3) ? 136 : z * 64;

    const float* Ap = A + (size_t)(b*NH + r) * NN * NN;
    const __nv_bfloat16* Yh = g_Yh + (size_t)(b*NH + r) * NN * YW;
    const __nv_bfloat16* Yl = g_Yl + (size_t)(b*NH + r) * NN * YW;
    float* Zb = g_Zh + (size_t)(b*NH + r) * NRH;
    float* Db = g_D + (b*NH + r) * NN;

    __shared__ __align__(16) __nv_bfloat16 sA[4][64][24];
    __shared__ __align__(16) __nv_bfloat16 sBh[4][16][120];
    __shared__ __align__(16) __nv_bfloat16 sBl[4][16][120];

    int tid = threadIdx.x, lane = tid & 31, wid = tid >> 5;
    int wm = wid & 3, wn = wid >> 2;

    {
        int st = tid >> 6;
        int rem = tid & 63;
        int arr = rem >> 5, row = (rem >> 1) & 15, sg = rem & 1;
        __nv_bfloat16* p = arr ? &sBl[st][row][104 + sg*8] : &sBh[st][row][104 + sg*8];
        *(uint4*)p = make_uint4(0u,0u,0u,0u);
    }

    float acc[7][4];
    #pragma unroll
    for (int f = 0; f < 7; ++f)
        #pragma unroll
        for (int q = 0; q < 4; ++q) acc[f][q] = 0.f;

    uint32_t aBase = smem_u32(&sA[0][wm*16 + (lane & 15)][(lane >> 4) * 8]);
    uint32_t bHBase = smem_u32(&sBh[0][lane & 15][(lane >> 4) * 8]);
    uint32_t bLBase = smem_u32(&sBl[0][lane & 15][(lane >> 4) * 8]);

    float4 av = loadA16(Ap, m0, 0, tid);
    issueB16(Yh, Yl, 0, NN, tid, sBh[0], sBl[0]);
    cp_commit();
    stsA16(av, sA[0], tid);
    av = loadA16(Ap, m0, 16, tid);
    issueB16(Yh, Yl, 16, NN, tid, sBh[1], sBl[1]);
    cp_commit();
    stsA16(av, sA[1], tid);
    av = loadA16(Ap, m0, 32, tid);
    issueB16(Yh, Yl, 32, NN, tid, sBh[2], sBl[2]);
    cp_commit();
    stsA16(av, sA[2], tid);
    av = loadA16(Ap, m0, 48, tid);

    #pragma unroll 1
    for (int i = 0; i < 13; ++i) {
        cp_wait_group<2>();
        __syncthreads();
        int nc = i + 3;
        if (nc < 13)
            issueB16(Yh, Yl, nc * 16, NN, tid, sBh[nc & 3], sBl[nc & 3]);
        cp_commit();
        int s = i & 3;
        compute_tile(acc, aBase + s*3072, bHBase + s*3840, bLBase + s*3840, wn);
        if (nc < 13) {
            stsA16(av, sA[nc & 3], tid);
            if (nc + 1 < 13) av = loadA16(Ap, m0, (nc + 1) * 16, tid);
        }
    }

    int g = lane >> 2, tg = lane & 3;
    #pragma unroll
    for (int f = 0; f < 7; ++f) {
        int c = wn*56 + f*8 + tg*2;
        #pragma unroll
        for (int h2 = 0; h2 < 2; ++h2) {
            int row = m0 + wm*16 + g + h2*8;
            if (row >= NN) continue;
            if (c <= 98)
                *(float2*)(Zb + row*HD + c) = make_float2(acc[f][2*h2], acc[f][2*h2 + 1]);
            else if (c == HD)
                Db[row] = acc[f][2*h2];
        }
    }
}

// ---------------- zero Zt1/Dt1 accumulators ----------------
__global__ void k_zero1()
{
    int i = blockIdx.x * 256 + threadIdx.x;
    if (i < BS*NRH) g_Zt[(size_t)BS*NRH + i] = 0.f;
    if (i < BS*NN)  g_Dt[BS*NN + i] = 0.f;
}

// ---------------- t=1 grouped A-GEMM (4-stage K16, wait<2>): atomic partials, 4 heads/CTA ----------------
__global__ __launch_bounds__(256) void k_agemm1_tc(const float* __restrict__ A,
                                                   const float* __restrict__ endv)
{
    int z = blockIdx.x, b = blockIdx.y, rg = blockIdx.z;
    int m0 = (z == 3) ? 136 : z * 64;
    int rbase = rg * 4;
    int nr = min(4, NH - rbase);
    const int NCH = nr * 13;

    __shared__ __align__(16) __nv_bfloat16 sA[4][64][24];
    __shared__ __align__(16) __nv_bfloat16 sBh[4][16][120];
    __shared__ __align__(16) __nv_bfloat16 sBl[4][16][120];

    int tid = threadIdx.x, lane = tid & 31, wid = tid >> 5;
    int wm = wid & 3, wn = wid >> 2;

    {
        int st = tid >> 6;
        int rem = tid & 63;
        int arr = rem >> 5, row = (rem >> 1) & 15, sg = rem & 1;
        __nv_bfloat16* p = arr ? &sBl[st][row][104 + sg*8] : &sBh[st][row][104 + sg*8];
        *(uint4*)p = make_uint4(0u,0u,0u,0u);
    }

    float acc[7][4];
    #pragma unroll
    for (int f = 0; f < 7; ++f)
        #pragma unroll
        for (int q = 0; q < 4; ++q) acc[f][q] = 0.f;

    uint32_t aBase = smem_u32(&sA[0][wm*16 + (lane & 15)][(lane >> 4) * 8]);
    uint32_t bHBase = smem_u32(&sBh[0][lane & 15][(lane >> 4) * 8]);
    uint32_t bLBase = smem_u32(&sBl[0][lane & 15][(lane >> 4) * 8]);

    auto chunkPtrs = [&](int idx, const float*& Ap, const __nv_bfloat16*& Yh,
                         const __nv_bfloat16*& Yl, int& cn) {
        int rn = rbase + idx / 13; cn = idx % 13;
        Ap = A + (size_t)(b*NH + rn) * NN * NN;
        Yh = g_Yh + (size_t)(b*NH + rn) * NN * YW;
        Yl = g_Yl + (size_t)(b*NH + rn) * NN * YW;
    };

    const float* Ap; const __nv_bfloat16 *Yh, *Yl; int cn;
    chunkPtrs(0, Ap, Yh, Yl, cn);
    float4 av = loadA16(Ap, m0, 0, tid);
    issueB16(Yh, Yl, 0, NN, tid, sBh[0], sBl[0]);
    cp_commit();
    stsA16(av, sA[0], tid);
    chunkPtrs(1, Ap, Yh, Yl, cn);
    av = loadA16(Ap, m0, cn * 16, tid);
    issueB16(Yh, Yl, cn * 16, NN, tid, sBh[1], sBl[1]);
    cp_commit();
    stsA16(av, sA[1], tid);
    chunkPtrs(2, Ap, Yh, Yl, cn);
    av = loadA16(Ap, m0, cn * 16, tid);
    issueB16(Yh, Yl, cn * 16, NN, tid, sBh[2], sBl[2]);
    cp_commit();
    stsA16(av, sA[2], tid);
    chunkPtrs(3, Ap, Yh, Yl, cn);
    av = loadA16(Ap, m0, cn * 16, tid);

    #pragma unroll 1
    for (int i = 0; i < NCH; ++i) {
        cp_wait_group<2>();
        __syncthreads();
        int nc = i + 3;
        if (nc < NCH) {
            const float* Ap2; const __nv_bfloat16 *Yh2, *Yl2; int cn2;
            chunkPtrs(nc, Ap2, Yh2, Yl2, cn2);
            issueB16(Yh2, Yl2, cn2 * 16, NN, tid, sBh[nc & 3], sBl[nc & 3]);
        }
        cp_commit();
        int s = i & 3;
        compute_tile(acc, aBase + s*3072, bHBase + s*3840, bLBase + s*3840, wn);
        if (nc < NCH) {
            stsA16(av, sA[nc & 3], tid);
            if (nc + 1 < NCH) {
                chunkPtrs(nc + 1, Ap, Yh, Yl, cn);
                av = loadA16(Ap, m0, cn * 16, tid);
            }
        }
    }

    int rowlo = (z == 3) ? 192 : m0;
    int g = lane >> 2, tg = lane & 3;
    #pragma unroll
    for (int f = 0; f < 7; ++f) {
        int nb = wn*56 + f*8;
        #pragma unroll
        for (int q = 0; q < 4; ++q) {
            int row = m0 + wm*16 + g + (q >> 1) * 8;
            int col = nb + tg*2 + (q & 1);
            if (row >= rowlo && row < NN) {
                float e = endv[b*NN + row];
                if (col < HD)
                    atomicAdd(&g_Zt[(size_t)(BS + b) * NRH + row*HD + col], acc[f][q] * e);
                else if (col == HD)
                    atomicAdd(&g_Dt[BS*NN + b*NN + row], acc[f][q] * e);
            }
        }
    }
}

// ---------------- Dt0[b,i] = end * sum_r D0[b,r,i] ----------------
__global__ void k_dt(const float* __restrict__ endv)
{
    int idx = blockIdx.x * 256 + threadIdx.x;
    if (idx >= BS*NN) return;
    int b = idx / NN, i = idx - b*NN;
    float acc = 0.f;
    #pragma unroll 2
    for (int r = 0; r < NH; ++r) acc += g_D[(b*NH + r)*NN + i];
    g_Dt[idx] = acc * endv[idx];
}

// ---------------- fused trans-mix + r-sum over Zh0 (R14 version) ----------------
__global__ void k_transsum(const float* __restrict__ trans)
{
    int b = blockIdx.y;
    __shared__ float ts[NH*NH];
    for (int i = threadIdx.x; i < NH*NH; i += 256) ts[i] = trans[b*NH*NH + i];
    __syncthreads();

    int x0 = blockIdx.x * 512 + threadIdx.x;
    int x1 = x0 + 256;
    const float* Zb = g_Zh + (size_t)b * NH * NRH;
    float acc0[NH], acc1[NH];
    float sv0 = 0.f, sv1 = 0.f;
    #pragma unroll
    for (int s = 0; s < NH; ++s) { acc0[s] = 0.f; acc1[s] = 0.f; }

    for (int r = 0; r < NH; ++r) {
        float v0 = (x0 < NRH) ? Zb[(size_t)r*NRH + x0] : 0.f;
        float v1 = (x1 < NRH) ? Zb[(size_t)r*NRH + x1] : 0.f;
        sv0 += v0; sv1 += v1;
        #pragma unroll
        for (int s = 0; s < NH; ++s) {
            float tv = ts[r*NH + s];
            acc0[s] += v0 * tv;
            acc1[s] += v1 * tv;
        }
    }
    int j0 = x0 / HD, d0 = x0 - j0*HD;
    int j1 = x1 / HD, d1 = x1 - j1*HD;
    size_t p0 = (size_t)j0 * XW + d0;
    size_t p1 = (size_t)j1 * XW + d1;
    #pragma unroll
    for (int s = 0; s < NH; ++s) {
        size_t ob = (size_t)(b*NH + s) * TRS;
        if (x0 < NRH) {
            float v = acc0[s];
            __nv_bfloat16 h = __float2bfloat16(v);
            g_Trh[ob + p0] = h;
            g_Trl[ob + p0] = __float2bfloat16(v - __bfloat162float(h));
            if (d0 >= 96) { g_Trh[ob + p0 + 4] = __float2bfloat16(0.f);
                            g_Trl[ob + p0 + 4] = __float2bfloat16(0.f); }
        }
        if (x1 < NRH) {
            float v = acc1[s];
            __nv_bfloat16 h = __float2bfloat16(v);
            g_Trh[ob + p1] = h;
            g_Trl[ob + p1] = __float2bfloat16(v - __bfloat162float(h));
            if (d1 >= 96) { g_Trh[ob + p1 + 4] = __float2bfloat16(0.f);
                            g_Trl[ob + p1 + 4] = __float2bfloat16(0.f); }
        }
    }
    if (x0 < NRH) g_Zsum[(size_t)b * NRH + x0] = sv0;
    if (x1 < NRH) g_Zsum[(size_t)b * NRH + x1] = sv1;
}

// ---------------- Zt0 = rowscale(end) * (Zsum[b] @ Wpad)  grid (2, BS) ----------------
__global__ void k_zt0(const float* __restrict__ wvs, const float* __restrict__ endv)
{
    int mt = blockIdx.x;
    int b = blockIdx.y;
    const float* In = g_Zsum + (size_t)b * NRH;
    const float* W = wvs + (size_t)69 * (HD*HD);
    const float* rs = endv + b*NN;
    float* Out = g_Zt + (size_t)b * NRH;

    __shared__ float As[128][33];
    __shared__ float Bs[32][128];
    int tid = threadIdx.x;
    int tx = tid & 15, ty = tid >> 4;

    float acc[8][8];
    #pragma unroll
    for (int i = 0; i < 8; ++i)
        #pragma unroll
        for (int j = 0; j < 8; ++j) acc[i][j] = 0.f;

    for (int k0 = 0; k0 < HD; k0 += 32) {
        int klen = min(32, HD - k0);
        #pragma unroll
        for (int l = 0; l < 4; ++l) {
            int idx = tid + l*256;
            int row = idx >> 3;
            int c4 = (idx & 7) << 2;
            int grow = mt*128 + row;
            float4 v = make_float4(0.f,0.f,0.f,0.f);
            if (grow < NN && c4 < klen)
                v = *(const float4*)(In + (size_t)grow*HD + k0 + c4);
            As[row][c4+0] = v.x; As[row][c4+1] = v.y;
            As[row][c4+2] = v.z; As[row][c4+3] = v.w;
        }
        #pragma unroll
        for (int l = 0; l < 4; ++l) {
            int idx = tid + l*256;
            int kk = idx >> 5;
            int c4 = (idx & 31) << 2;
            float4 v = make_float4(0.f,0.f,0.f,0.f);
            if (kk < klen && c4 < HD)
                v = *(const float4*)(W + (size_t)(k0+kk)*HD + c4);
            *(float4*)&Bs[kk][c4] = v;
        }
        __syncthreads();
        #pragma unroll 4
        for (int kk = 0; kk < klen; ++kk) {
            float a[8];
            #pragma unroll
            for (int i = 0; i < 8; ++i) a[i] = As[ty*8 + i][kk];
            float4 b0 = *(float4*)&Bs[kk][tx*8];
            float4 b1 = *(float4*)&Bs[kk][tx*8 + 4];
            float bb[8] = {b0.x,b0.y,b0.z,b0.w,b1.x,b1.y,b1.z,b1.w};
            #pragma unroll
            for (int i = 0; i < 8; ++i)
                #pragma unroll
                for (int j = 0; j < 8; ++j)
                    acc[i][j] += a[i] * bb[j];
        }
        __syncthreads();
    }
    #pragma unroll
    for (int i = 0; i < 8; ++i) {
        int grow = mt*128 + ty*8 + i;
        if (grow < NN) {
            float sc = rs[grow];
            #pragma unroll
            for (int j = 0; j < 8; ++j) {
                int c = tx*8 + j;
                if (c < HD) Out[(size_t)grow*HD + c] = acc[i][j] * sc;
            }
        }
    }
}

// ---------------- epilogue: warp-shuffle reduction ----------------
__global__ void k_out(float* __restrict__ out)
{
    int bn = blockIdx.x;
    int b = bn / NN, n = bn - b*NN;
    int tid = threadIdx.x, lane = tid & 31, wid = tid >> 5;
    __shared__ float red[5];

    float z[2], dt[2];
    #pragma unroll
    for (int t = 0; t < 2; ++t) {
        float zv = 0.f, p = 0.f;
        if (tid < HD) {
            float dd = g_Dt[t*BS*NN + b*NN + n];
            zv = g_Zt[(size_t)(t*BS + b) * NRH + n*HD + tid] / (dd + EPSV);
            p = g_Sq[b*HD + tid] * zv;
        }
        z[t] = zv;
        #pragma unroll
        for (int o = 16; o > 0; o >>= 1) p += __shfl_down_sync(0xffffffffu, p, o);
        if (lane == 0) red[wid] = p;
        __syncthreads();
        if (tid == 0) red[4] = (red[0] + red[1]) + (red[2] + red[3]);
        __syncthreads();
        dt[t] = red[4] * 0.1f;   // / sqrt(100)
        __syncthreads();
    }
    float m = fmaxf(dt[0], dt[1]);
    float e0 = expf(dt[0] - m), e1 = expf(dt[1] - m);
    float inv = 1.f / (e0 + e1);
    if (tid < HD)
        out[(size_t)bn * HD + tid] = (e0 * z[0] + e1 * z[1]) * inv;
}

// ---------------- launch (multi-stream, graph-capturable fork/join) ----------------
extern "C" void kernel_launch(void* const* d_in, const int* in_sizes, int n_in,
                              void* d_out, int out_size)
{
    (void)in_sizes; (void)n_in; (void)out_size;
    const float* X     = (const float*)d_in[0];
    const float* A     = (const float*)d_in[1];
    const float* start = (const float*)d_in[2];
    const float* endv  = (const float*)d_in[3];
    const float* uni   = (const float*)d_in[4];
    const float* trans = (const float*)d_in[5];
    const float* S     = (const float*)d_in[6];
    const float* wvs   = (const float*)d_in[7];
    const float* wqw   = (const float*)d_in[8];
    const float* wqb   = (const float*)d_in[9];
    float* out = (float*)d_out;

    static cudaStream_t s1, s2, s3;
    static cudaEvent_t e0, e1, e2, e3, e4, e5, e6;
    static bool init = false;
    if (!init) {
        cudaStreamCreateWithFlags(&s1, cudaStreamNonBlocking);
        cudaStreamCreateWithFlags(&s2, cudaStreamNonBlocking);
        cudaStreamCreateWithFlags(&s3, cudaStreamNonBlocking);
        cudaEventCreateWithFlags(&e0, cudaEventDisableTiming);
        cudaEventCreateWithFlags(&e1, cudaEventDisableTiming);
        cudaEventCreateWithFlags(&e2, cudaEventDisableTiming);
        cudaEventCreateWithFlags(&e3, cudaEventDisableTiming);
        cudaEventCreateWithFlags(&e4, cudaEventDisableTiming);
        cudaEventCreateWithFlags(&e5, cudaEventDisableTiming);
        cudaEventCreateWithFlags(&e6, cudaEventDisableTiming);
        cudaFuncSetAttribute((const void*)k_ygemm_tc,
                             cudaFuncAttributeMaxDynamicSharedMemorySize, YG_SMEM);
        init = true;
    }

    cudaEventRecord(e0, 0);
    cudaStreamWaitEvent(s1, e0, 0);
    cudaStreamWaitEvent(s2, e0, 0);
    cudaStreamWaitEvent(s3, e0, 0);

    k_sq<<<(BS*HD + 7) / 8, 256, 0, s1>>>(S, wqw, wqb);
    k_splitW<<<(70*HD*WW + 255)/256, 256, 0, s2>>>(wvs);
    k_zero1<<<(BS*NRH + 255)/256, 256, 0, s3>>>();
    k_splitX<<<(BS*TRS + 255)/256, 256>>>(X);

    cudaEventRecord(e1, s2);
    cudaStreamWaitEvent(0, e1, 0);

    dim3 gg(NH, BS, 4);
    k_ygemm_tc<<<gg, 256, YG_SMEM>>>(0, uni, start, trans);
    k_agemm_tc<<<gg, 256>>>(A);

    cudaEventRecord(e2, 0);
    cudaStreamWaitEvent(s1, e2, 0);
    k_dt<<<(BS*NN + 255)/256, 256, 0, s1>>>(endv);

    k_transsum<<<dim3((NRH + 511)/512, BS), 256>>>(trans);

    cudaEventRecord(e3, 0);
    cudaStreamWaitEvent(s2, e3, 0);
    k_zt0<<<dim3(2, BS), 256, 0, s2>>>(wvs, endv);

    k_ygemm_tc<<<gg, 256, YG_SMEM>>>(1, uni, start, trans);
    cudaEventRecord(e4, s3);
    cudaStreamWaitEvent(0, e4, 0);
    k_agemm1_tc<<<dim3(4, BS, 9), 256>>>(A, endv);

    cudaEventRecord(e5, s1);
    cudaStreamWaitEvent(0, e5, 0);
    cudaEventRecord(e6, s2);
    cudaStreamWaitEvent(0, e6, 0);
    k_out<<<BS*NN, 128>>>(out);
}